// round 5
// baseline (speedup 1.0000x reference)
#include <cuda_runtime.h>

#define MAXTOK 16384

// ---------------- scratch (device globals; no allocation allowed) ----------
__device__ float g_feat[MAXTOK * 88];   // [tok][88]: 0..44 coord, 45..83 dihedral
__device__ float g_h1[MAXTOK * 256];    // sorted-token order
__device__ float g_h2[MAXTOK * 128];    // sorted-token order
__device__ float g_E1[20 * 256];
__device__ float g_C1[10 * 256];
__device__ int g_hist[20];
__device__ int g_base[20];
__device__ int g_cursor[20];
__device__ int g_order[MAXTOK];         // sorted pos -> original token
__device__ int g_done;

typedef unsigned long long ull;

static __device__ __forceinline__ ull f2pack(float lo, float hi) {
    ull r; asm("mov.b64 %0,{%1,%2};" : "=l"(r) : "f"(lo), "f"(hi)); return r;
}
static __device__ __forceinline__ void f2unpack(ull v, float& lo, float& hi) {
    asm("mov.b64 {%0,%1},%2;" : "=f"(lo), "=f"(hi) : "l"(v));
}
static __device__ __forceinline__ ull ffma2(ull a, ull b, ull c) {
    ull d; asm("fma.rn.f32x2 %0,%1,%2,%3;" : "=l"(d) : "l"(a), "l"(b), "l"(c)); return d;
}
static __device__ __forceinline__ ull fadd2(ull a, ull b) {
    ull d; asm("add.rn.f32x2 %0,%1,%2;" : "=l"(d) : "l"(a), "l"(b)); return d;
}

// ---------------- setup: E1/C1 tables + per-token features + hist + scan ----
__global__ void __launch_bounds__(256)
k_setup(const float* __restrict__ aa_emb, const float* __restrict__ ch_emb,
        const float* __restrict__ W1, const float* __restrict__ b1,
        const float* __restrict__ xyz, const float* __restrict__ ori,
        const float* __restrict__ dih, const int* __restrict__ seq,
        int ntok, int nfeatblk) {
    int b = blockIdx.x, tid = threadIdx.x;
    if (b < 30) {  // precompute E1 / C1
        int j = tid;
        if (b < 20) {
            float acc = b1[j];
#pragma unroll 8
            for (int k = 0; k < 128; k++) acc += aa_emb[b * 128 + k] * W1[k * 256 + j];
            g_E1[b * 256 + j] = acc;
        } else {
            int c = b - 20;
            float acc = 0.f;
            if (c != 0) {
#pragma unroll 8
                for (int k = 0; k < 128; k++)
                    acc += ch_emb[c * 128 + k] * W1[(1067 + k) * 256 + j];
            }
            g_C1[c * 256 + j] = acc;
        }
        return;
    }
    int t = (b - 30) * 256 + tid;
    if (t < ntok) {
        const float* X = xyz + t * 45;
        float ca0 = X[3], ca1 = X[4], ca2 = X[5];   // CA_IDX = 1
        float o[9];
#pragma unroll
        for (int i = 0; i < 9; i++) o[i] = ori[t * 9 + i];
        float* F = g_feat + t * 88;
#pragma unroll
        for (int a = 0; a < 15; a++) {
            float rx = X[a * 3 + 0] - ca0;
            float ry = X[a * 3 + 1] - ca1;
            float rz = X[a * 3 + 2] - ca2;
#pragma unroll
            for (int i = 0; i < 3; i++)  // O^T @ rel
                F[a * 3 + i] = o[i] * rx + o[3 + i] * ry + o[6 + i] * rz;
        }
        const float fb[6] = {1.f, 2.f, 3.f, 1.f, 0.5f, 1.f / 3.f};
#pragma unroll
        for (int d = 0; d < 3; d++) {
            float x = dih[t * 3 + d];
            int bo = 45 + d * 13;
            F[bo] = x;
#pragma unroll
            for (int u = 0; u < 6; u++) {
                F[bo + 1 + u] = sinf(fb[u] * x);
                F[bo + 7 + u] = cosf(fb[u] * x);
            }
        }
        atomicAdd(&g_hist[seq[t]], 1);
    }
    __syncthreads();
    if (tid == 0) {
        __threadfence();
        if (atomicAdd(&g_done, 1) == nfeatblk - 1) {  // last feat block: scan
            __threadfence();
            int s = 0;
            for (int i = 0; i < 20; i++) {
                int h = atomicAdd(&g_hist[i], 0);
                g_base[i] = s; s += h;
            }
            atomicExch(&g_done, 0);  // reset for next replay
        }
    }
}

// ---------------- block-aggregated counting-sort scatter ---------------------
__global__ void __launch_bounds__(256)
k_scatter(const int* __restrict__ seq, int ntok) {
    __shared__ int lh[20], lb[20], lc[20];
    int tid = threadIdx.x;
    if (tid < 20) { lh[tid] = 0; lc[tid] = 0; }
    __syncthreads();
    int t = blockIdx.x * 256 + tid;
    int s = -1;
    if (t < ntok) { s = seq[t]; atomicAdd(&lh[s], 1); }
    __syncthreads();
    if (tid < 20 && lh[tid] > 0) lb[tid] = atomicAdd(&g_cursor[tid], lh[tid]);
    __syncthreads();
    if (t < ntok) {
        int p = atomicAdd(&lc[s], 1);
        g_order[g_base[s] + lb[s] + p] = t;
    }
}

// ---------------- layer 1 (dense+coord merged), grouped by aa type -----------
// grid (20, 7); 512 thr; K=84, J=256; 64 tokens/group; token-paired FFMA2.
__global__ void __launch_bounds__(512)
k_l1(const float* __restrict__ W1, const int* __restrict__ cidx) {
    extern __shared__ __align__(16) float sm[];
    float* Ws  = sm;            // 84*256 = 21504
    float* C1s = sm + 21504;    // 2560
    float* E1s = sm + 24064;    // 256
    float* xs  = sm + 24320;    // 84*68 = 5712
    int*   cs  = (int*)(sm + 30032);  // 64 ints
    int tid = threadIdx.x, s = blockIdx.x;
    if (s == 0 && blockIdx.y == 0 && tid < 20) g_cursor[tid] = 0;  // next replay
    for (int i = tid; i < 84 * 256; i += 512) {
        int r = i >> 8, c = i & 255;
        int src = (r < 45) ? (128 + s * 45 + r) : (1028 + r - 45);
        Ws[i] = W1[src * 256 + c];
    }
    for (int i = tid; i < 2560; i += 512) C1s[i] = g_C1[i];
    if (tid < 256) E1s[tid] = g_E1[s * 256 + tid];
    __syncthreads();

    int cnt = g_hist[s], base = g_base[s];
    int st = cnt * blockIdx.y / 7, en = cnt * (blockIdx.y + 1) / 7;
    int lane = tid & 31, w = tid >> 5;
    int jq = w & 3, th = w >> 2;
    int j0 = jq * 64 + lane, j1 = j0 + 32, T0 = th * 16;
    ull e0 = f2pack(E1s[j0], E1s[j0]);
    ull e1 = f2pack(E1s[j1], E1s[j1]);

    for (int g0 = st; g0 < en; g0 += 64) {
        int n = min(64, en - g0);
        __syncthreads();
        if (tid < 64) cs[tid] = (tid < n) ? cidx[g_order[base + g0 + tid]] : 0;
        // staging: conflict-free transpose (lane = k, float4 of 4 tokens)
        for (int it = w; it < 48; it += 16) {
            int kc = it % 3, tc = it / 3;
            int k = kc * 32 + lane;
            if (k < 84) {
                int tb = tc * 4;
                float v[4];
#pragma unroll
                for (int i = 0; i < 4; i++) {
                    int t = tb + i;
                    v[i] = (t < n) ? g_feat[(size_t)g_order[base + g0 + t] * 88 + k] : 0.f;
                }
                *(float4*)&xs[k * 68 + tb] = make_float4(v[0], v[1], v[2], v[3]);
            }
        }
        __syncthreads();
        ull a0[8], a1[8];
#pragma unroll
        for (int u = 0; u < 8; u++) {
            int ca = cs[T0 + 2 * u], cb = cs[T0 + 2 * u + 1];
            a0[u] = fadd2(e0, f2pack(C1s[ca * 256 + j0], C1s[cb * 256 + j0]));
            a1[u] = fadd2(e1, f2pack(C1s[ca * 256 + j1], C1s[cb * 256 + j1]));
        }
#pragma unroll 4
        for (int k = 0; k < 84; k++) {
            float w0 = Ws[k * 256 + j0], w1 = Ws[k * 256 + j1];
            ull wd0 = f2pack(w0, w0), wd1 = f2pack(w1, w1);
            const ulonglong2* xr = (const ulonglong2*)&xs[k * 68 + T0];
            ulonglong2 xa = xr[0], xb = xr[1], xc = xr[2], xd = xr[3];
            a0[0] = ffma2(xa.x, wd0, a0[0]); a1[0] = ffma2(xa.x, wd1, a1[0]);
            a0[1] = ffma2(xa.y, wd0, a0[1]); a1[1] = ffma2(xa.y, wd1, a1[1]);
            a0[2] = ffma2(xb.x, wd0, a0[2]); a1[2] = ffma2(xb.x, wd1, a1[2]);
            a0[3] = ffma2(xb.y, wd0, a0[3]); a1[3] = ffma2(xb.y, wd1, a1[3]);
            a0[4] = ffma2(xc.x, wd0, a0[4]); a1[4] = ffma2(xc.x, wd1, a1[4]);
            a0[5] = ffma2(xc.y, wd0, a0[5]); a1[5] = ffma2(xc.y, wd1, a1[5]);
            a0[6] = ffma2(xd.x, wd0, a0[6]); a1[6] = ffma2(xd.x, wd1, a1[6]);
            a0[7] = ffma2(xd.y, wd0, a0[7]); a1[7] = ffma2(xd.y, wd1, a1[7]);
        }
#pragma unroll
        for (int u = 0; u < 8; u++) {
            int ta = T0 + 2 * u;
            if (ta < n) {
                int pa = (base + g0 + ta) * 256;
                float va0, vb0, va1, vb1;
                f2unpack(a0[u], va0, vb0);
                f2unpack(a1[u], va1, vb1);
                g_h1[pa + j0] = fmaxf(va0, 0.f);
                g_h1[pa + j1] = fmaxf(va1, 0.f);
                if (ta + 1 < n) {
                    g_h1[pa + 256 + j0] = fmaxf(vb0, 0.f);
                    g_h1[pa + 256 + j1] = fmaxf(vb1, 0.f);
                }
            }
        }
    }
}

// ---------------- layer 2: h2 = relu(h1 @ W2 + b2) ---------------------------
// 256 thr (8 warps = 2 j-half x 4 token-16s); K=256, J=128; 64 tokens/group.
__global__ void __launch_bounds__(256)
k_l2(const float* __restrict__ W2, const float* __restrict__ b2, int ntok) {
    extern __shared__ __align__(16) float sm[];
    float* Ws = sm;            // 256*128 = 32768
    float* xs = sm + 32768;    // 256*68  = 17408
    int tid = threadIdx.x;
    if (blockIdx.x == 0 && tid < 20) g_hist[tid] = 0;  // next replay
    for (int i = tid * 4; i < 32768; i += 1024)
        *(float4*)&Ws[i] = *(const float4*)&W2[i];
    int lane = tid & 31, w = tid >> 5;
    int jh = w & 1, th = w >> 1;
    int j0 = jh * 64 + lane, j1 = j0 + 32, T0 = th * 16;
    ull bb0 = f2pack(b2[j0], b2[j0]), bb1 = f2pack(b2[j1], b2[j1]);
    int ngrp = (ntok + 63) >> 6;
    for (int u = blockIdx.x; u < ngrp; u += gridDim.x) {
        int t0 = u * 64;
        __syncthreads();
        // staging: lane = k, float4 of 4 tokens; coalesced LDG, conflict-free STS
        for (int it = w; it < 128; it += 8) {
            int kc = it & 7, tc = it >> 3;
            int k = kc * 32 + lane;
            int tb = t0 + tc * 4;
            float v0 = (tb + 0 < ntok) ? g_h1[(size_t)(tb + 0) * 256 + k] : 0.f;
            float v1 = (tb + 1 < ntok) ? g_h1[(size_t)(tb + 1) * 256 + k] : 0.f;
            float v2 = (tb + 2 < ntok) ? g_h1[(size_t)(tb + 2) * 256 + k] : 0.f;
            float v3 = (tb + 3 < ntok) ? g_h1[(size_t)(tb + 3) * 256 + k] : 0.f;
            *(float4*)&xs[k * 68 + tc * 4] = make_float4(v0, v1, v2, v3);
        }
        __syncthreads();
        ull a0[8], a1[8];
#pragma unroll
        for (int p = 0; p < 8; p++) { a0[p] = bb0; a1[p] = bb1; }
#pragma unroll 4
        for (int k = 0; k < 256; k++) {
            float w0 = Ws[k * 128 + j0], w1 = Ws[k * 128 + j1];
            ull wd0 = f2pack(w0, w0), wd1 = f2pack(w1, w1);
            const ulonglong2* xr = (const ulonglong2*)&xs[k * 68 + T0];
            ulonglong2 xa = xr[0], xb = xr[1], xc = xr[2], xd = xr[3];
            a0[0] = ffma2(xa.x, wd0, a0[0]); a1[0] = ffma2(xa.x, wd1, a1[0]);
            a0[1] = ffma2(xa.y, wd0, a0[1]); a1[1] = ffma2(xa.y, wd1, a1[1]);
            a0[2] = ffma2(xb.x, wd0, a0[2]); a1[2] = ffma2(xb.x, wd1, a1[2]);
            a0[3] = ffma2(xb.y, wd0, a0[3]); a1[3] = ffma2(xb.y, wd1, a1[3]);
            a0[4] = ffma2(xc.x, wd0, a0[4]); a1[4] = ffma2(xc.x, wd1, a1[4]);
            a0[5] = ffma2(xc.y, wd0, a0[5]); a1[5] = ffma2(xc.y, wd1, a1[5]);
            a0[6] = ffma2(xd.x, wd0, a0[6]); a1[6] = ffma2(xd.x, wd1, a1[6]);
            a0[7] = ffma2(xd.y, wd0, a0[7]); a1[7] = ffma2(xd.y, wd1, a1[7]);
        }
#pragma unroll
        for (int p = 0; p < 8; p++) {
            int ta = t0 + T0 + 2 * p;
            if (ta < ntok) {
                float va0, vb0, va1, vb1;
                f2unpack(a0[p], va0, vb0);
                f2unpack(a1[p], va1, vb1);
                g_h2[ta * 128 + j0] = fmaxf(va0, 0.f);
                g_h2[ta * 128 + j1] = fmaxf(va1, 0.f);
                if (ta + 1 < ntok) {
                    g_h2[(ta + 1) * 128 + j0] = fmaxf(vb0, 0.f);
                    g_h2[(ta + 1) * 128 + j1] = fmaxf(vb1, 0.f);
                }
            }
        }
    }
}

// ---------------- layers 3+4 fused ------------------------------------------
// 256 thr (8 warps = 2 j-half x 4 token-16s); 64 tokens/group.
__global__ void __launch_bounds__(256)
k_l34(const float* __restrict__ W3, const float* __restrict__ b3,
      const float* __restrict__ W4, const float* __restrict__ b4,
      float* __restrict__ out, int ntok) {
    extern __shared__ __align__(16) float sm[];
    float* W3s = sm;              // 16384
    float* W4s = sm + 16384;      // 16384
    float* xs  = sm + 32768;      // 128*68 = 8704
    float* hs  = sm + 41472;      // 128*68 = 8704
    int*   os  = (int*)(sm + 50176);  // 64 ints
    int tid = threadIdx.x;
    for (int i = tid * 4; i < 16384; i += 1024) {
        *(float4*)&W3s[i] = *(const float4*)&W3[i];
        *(float4*)&W4s[i] = *(const float4*)&W4[i];
    }
    int lane = tid & 31, w = tid >> 5;
    int jh = w & 1, th = w >> 1;
    int j0 = jh * 64 + lane, j1 = j0 + 32, T0 = th * 16;
    ull b30 = f2pack(b3[j0], b3[j0]), b31 = f2pack(b3[j1], b3[j1]);
    ull b40 = f2pack(b4[j0], b4[j0]), b41 = f2pack(b4[j1], b4[j1]);
    int ngrp = (ntok + 63) >> 6;
    for (int u = blockIdx.x; u < ngrp; u += gridDim.x) {
        int t0 = u * 64;
        __syncthreads();
        if (tid < 64) os[tid] = (t0 + tid < ntok) ? g_order[t0 + tid] : 0;
        for (int it = w; it < 64; it += 8) {
            int kc = it & 3, tc = it >> 2;
            int k = kc * 32 + lane;
            int tb = t0 + tc * 4;
            float v0 = (tb + 0 < ntok) ? g_h2[(size_t)(tb + 0) * 128 + k] : 0.f;
            float v1 = (tb + 1 < ntok) ? g_h2[(size_t)(tb + 1) * 128 + k] : 0.f;
            float v2 = (tb + 2 < ntok) ? g_h2[(size_t)(tb + 2) * 128 + k] : 0.f;
            float v3 = (tb + 3 < ntok) ? g_h2[(size_t)(tb + 3) * 128 + k] : 0.f;
            *(float4*)&xs[k * 68 + tc * 4] = make_float4(v0, v1, v2, v3);
        }
        __syncthreads();
        // ---- L3 ----
        ull a0[8], a1[8];
#pragma unroll
        for (int p = 0; p < 8; p++) { a0[p] = b30; a1[p] = b31; }
#pragma unroll 4
        for (int k = 0; k < 128; k++) {
            float w0 = W3s[k * 128 + j0], w1 = W3s[k * 128 + j1];
            ull wd0 = f2pack(w0, w0), wd1 = f2pack(w1, w1);
            const ulonglong2* xr = (const ulonglong2*)&xs[k * 68 + T0];
            ulonglong2 xa = xr[0], xb = xr[1], xc = xr[2], xd = xr[3];
            a0[0] = ffma2(xa.x, wd0, a0[0]); a1[0] = ffma2(xa.x, wd1, a1[0]);
            a0[1] = ffma2(xa.y, wd0, a0[1]); a1[1] = ffma2(xa.y, wd1, a1[1]);
            a0[2] = ffma2(xb.x, wd0, a0[2]); a1[2] = ffma2(xb.x, wd1, a1[2]);
            a0[3] = ffma2(xb.y, wd0, a0[3]); a1[3] = ffma2(xb.y, wd1, a1[3]);
            a0[4] = ffma2(xc.x, wd0, a0[4]); a1[4] = ffma2(xc.x, wd1, a1[4]);
            a0[5] = ffma2(xc.y, wd0, a0[5]); a1[5] = ffma2(xc.y, wd1, a1[5]);
            a0[6] = ffma2(xd.x, wd0, a0[6]); a1[6] = ffma2(xd.x, wd1, a1[6]);
            a0[7] = ffma2(xd.y, wd0, a0[7]); a1[7] = ffma2(xd.y, wd1, a1[7]);
        }
#pragma unroll
        for (int p = 0; p < 8; p++) {
            float va0, vb0, va1, vb1;
            f2unpack(a0[p], va0, vb0);
            f2unpack(a1[p], va1, vb1);
            *(ull*)&hs[j0 * 68 + T0 + 2 * p] = f2pack(fmaxf(va0, 0.f), fmaxf(vb0, 0.f));
            *(ull*)&hs[j1 * 68 + T0 + 2 * p] = f2pack(fmaxf(va1, 0.f), fmaxf(vb1, 0.f));
        }
        __syncthreads();
        // ---- L4 ----
#pragma unroll
        for (int p = 0; p < 8; p++) { a0[p] = b40; a1[p] = b41; }
#pragma unroll 4
        for (int k = 0; k < 128; k++) {
            float w0 = W4s[k * 128 + j0], w1 = W4s[k * 128 + j1];
            ull wd0 = f2pack(w0, w0), wd1 = f2pack(w1, w1);
            const ulonglong2* xr = (const ulonglong2*)&hs[k * 68 + T0];
            ulonglong2 xa = xr[0], xb = xr[1], xc = xr[2], xd = xr[3];
            a0[0] = ffma2(xa.x, wd0, a0[0]); a1[0] = ffma2(xa.x, wd1, a1[0]);
            a0[1] = ffma2(xa.y, wd0, a0[1]); a1[1] = ffma2(xa.y, wd1, a1[1]);
            a0[2] = ffma2(xb.x, wd0, a0[2]); a1[2] = ffma2(xb.x, wd1, a1[2]);
            a0[3] = ffma2(xb.y, wd0, a0[3]); a1[3] = ffma2(xb.y, wd1, a1[3]);
            a0[4] = ffma2(xc.x, wd0, a0[4]); a1[4] = ffma2(xc.x, wd1, a1[4]);
            a0[5] = ffma2(xc.y, wd0, a0[5]); a1[5] = ffma2(xc.y, wd1, a1[5]);
            a0[6] = ffma2(xd.x, wd0, a0[6]); a1[6] = ffma2(xd.x, wd1, a1[6]);
            a0[7] = ffma2(xd.y, wd0, a0[7]); a1[7] = ffma2(xd.y, wd1, a1[7]);
        }
#pragma unroll
        for (int p = 0; p < 8; p++) {
            int ta = T0 + 2 * p;
            if (t0 + ta < ntok) {
                float va0, vb0, va1, vb1;
                f2unpack(a0[p], va0, vb0);
                f2unpack(a1[p], va1, vb1);
                int oa = os[ta];
                out[oa * 128 + j0] = va0;
                out[oa * 128 + j1] = va1;
                if (t0 + ta + 1 < ntok) {
                    int ob = os[ta + 1];
                    out[ob * 128 + j0] = vb0;
                    out[ob * 128 + j1] = vb1;
                }
            }
        }
    }
}

// ---------------- launch ----------------------------------------------------
extern "C" void kernel_launch(void* const* d_in, const int* in_sizes, int n_in,
                              void* d_out, int out_size) {
    const int*   seq    = (const int*)  d_in[0];
    const float* xyz    = (const float*)d_in[1];
    const float* dih    = (const float*)d_in[2];
    const int*   cidx   = (const int*)  d_in[3];
    const float* ori    = (const float*)d_in[4];
    /* d_in[5] = atom_mask : unused by reference */
    const float* aa_emb = (const float*)d_in[6];
    const float* ch_emb = (const float*)d_in[7];
    const float* W1 = (const float*)d_in[8];
    const float* b1 = (const float*)d_in[9];
    const float* W2 = (const float*)d_in[10];
    const float* b2 = (const float*)d_in[11];
    const float* W3 = (const float*)d_in[12];
    const float* b3 = (const float*)d_in[13];
    const float* W4 = (const float*)d_in[14];
    const float* b4 = (const float*)d_in[15];
    float* out = (float*)d_out;
    int ntok = in_sizes[0];
    if (ntok > MAXTOK) ntok = MAXTOK;

    int nfeatblk = (ntok + 255) / 256;
    const int SMEM1  = (30032 + 64) * 4;              // 120384 B
    const int SMEM2  = (32768 + 17408) * 4;           // 200704 B
    const int SMEM34 = (50176 + 64) * 4;              // 200960 B
    cudaFuncSetAttribute(k_l1,  cudaFuncAttributeMaxDynamicSharedMemorySize, SMEM1);
    cudaFuncSetAttribute(k_l2,  cudaFuncAttributeMaxDynamicSharedMemorySize, SMEM2);
    cudaFuncSetAttribute(k_l34, cudaFuncAttributeMaxDynamicSharedMemorySize, SMEM34);

    k_setup<<<30 + nfeatblk, 256>>>(aa_emb, ch_emb, W1, b1, xyz, ori, dih, seq,
                                    ntok, nfeatblk);
    k_scatter<<<(ntok + 255) / 256, 256>>>(seq, ntok);
    k_l1<<<dim3(20, 7), 512, SMEM1>>>(W1, cidx);
    k_l2<<<148, 256, SMEM2>>>(W2, b2, ntok);
    k_l34<<<148, 256, SMEM34>>>(W3, b3, W4, b4, out, ntok);
}

// round 6
// speedup vs baseline: 1.0005x; 1.0005x over previous
#include <cuda_runtime.h>

#define MAXTOK 16384

// ---------------- scratch (device globals; no allocation allowed) ----------
__device__ float g_feat[MAXTOK * 88];   // [tok][88]: 0..44 coord, 45..83 dihedral
__device__ float g_h1[MAXTOK * 256];    // sorted-token order
__device__ float g_h2[MAXTOK * 128];    // sorted-token order
__device__ float g_E1[20 * 256];
__device__ float g_C1[10 * 256];
__device__ int g_hist[20];
__device__ int g_base[20];
__device__ int g_cursor[20];
__device__ int g_order[MAXTOK];         // sorted pos -> original token
__device__ int g_done;

typedef unsigned long long ull;

static __device__ __forceinline__ ull f2pack(float lo, float hi) {
    ull r; asm("mov.b64 %0,{%1,%2};" : "=l"(r) : "f"(lo), "f"(hi)); return r;
}
static __device__ __forceinline__ void f2unpack(ull v, float& lo, float& hi) {
    asm("mov.b64 {%0,%1},%2;" : "=f"(lo), "=f"(hi) : "l"(v));
}
static __device__ __forceinline__ ull ffma2(ull a, ull b, ull c) {
    ull d; asm("fma.rn.f32x2 %0,%1,%2,%3;" : "=l"(d) : "l"(a), "l"(b), "l"(c)); return d;
}
static __device__ __forceinline__ ull fadd2(ull a, ull b) {
    ull d; asm("add.rn.f32x2 %0,%1,%2;" : "=l"(d) : "l"(a), "l"(b)); return d;
}

// ---------------- setup: E1/C1 tables + per-token features + hist + scan ----
__global__ void __launch_bounds__(256)
k_setup(const float* __restrict__ aa_emb, const float* __restrict__ ch_emb,
        const float* __restrict__ W1, const float* __restrict__ b1,
        const float* __restrict__ xyz, const float* __restrict__ ori,
        const float* __restrict__ dih, const int* __restrict__ seq,
        int ntok, int nfeatblk) {
    int b = blockIdx.x, tid = threadIdx.x;
    if (b < 30) {  // precompute E1 / C1
        int j = tid;
        if (b < 20) {
            float acc = b1[j];
#pragma unroll 8
            for (int k = 0; k < 128; k++) acc += aa_emb[b * 128 + k] * W1[k * 256 + j];
            g_E1[b * 256 + j] = acc;
        } else {
            int c = b - 20;
            float acc = 0.f;
            if (c != 0) {
#pragma unroll 8
                for (int k = 0; k < 128; k++)
                    acc += ch_emb[c * 128 + k] * W1[(1067 + k) * 256 + j];
            }
            g_C1[c * 256 + j] = acc;
        }
        return;
    }
    int t = (b - 30) * 256 + tid;
    if (t < ntok) {
        const float* X = xyz + t * 45;
        float ca0 = X[3], ca1 = X[4], ca2 = X[5];   // CA_IDX = 1
        float o[9];
#pragma unroll
        for (int i = 0; i < 9; i++) o[i] = ori[t * 9 + i];
        float* F = g_feat + t * 88;
#pragma unroll
        for (int a = 0; a < 15; a++) {
            float rx = X[a * 3 + 0] - ca0;
            float ry = X[a * 3 + 1] - ca1;
            float rz = X[a * 3 + 2] - ca2;
#pragma unroll
            for (int i = 0; i < 3; i++)  // O^T @ rel
                F[a * 3 + i] = o[i] * rx + o[3 + i] * ry + o[6 + i] * rz;
        }
        const float fb[6] = {1.f, 2.f, 3.f, 1.f, 0.5f, 1.f / 3.f};
#pragma unroll
        for (int d = 0; d < 3; d++) {
            float x = dih[t * 3 + d];
            int bo = 45 + d * 13;
            F[bo] = x;
#pragma unroll
            for (int u = 0; u < 6; u++) {
                F[bo + 1 + u] = sinf(fb[u] * x);
                F[bo + 7 + u] = cosf(fb[u] * x);
            }
        }
        atomicAdd(&g_hist[seq[t]], 1);
    }
    __syncthreads();
    if (tid == 0) {
        __threadfence();
        if (atomicAdd(&g_done, 1) == nfeatblk - 1) {  // last feat block: scan
            __threadfence();
            int s = 0;
            for (int i = 0; i < 20; i++) {
                int h = atomicAdd(&g_hist[i], 0);
                g_base[i] = s; s += h;
            }
            atomicExch(&g_done, 0);  // reset for next replay
        }
    }
}

// ---------------- block-aggregated counting-sort scatter ---------------------
__global__ void __launch_bounds__(256)
k_scatter(const int* __restrict__ seq, int ntok) {
    __shared__ int lh[20], lb[20], lc[20];
    int tid = threadIdx.x;
    if (tid < 20) { lh[tid] = 0; lc[tid] = 0; }
    __syncthreads();
    int t = blockIdx.x * 256 + tid;
    int s = -1;
    if (t < ntok) { s = seq[t]; atomicAdd(&lh[s], 1); }
    __syncthreads();
    if (tid < 20 && lh[tid] > 0) lb[tid] = atomicAdd(&g_cursor[tid], lh[tid]);
    __syncthreads();
    if (t < ntok) {
        int p = atomicAdd(&lc[s], 1);
        g_order[g_base[s] + lb[s] + p] = t;
    }
}

// ---------------- layer 1 (dense+coord merged), grouped by aa type -----------
// grid (20, 7); 512 thr; K=84, J=256; 64 tokens/group; token-paired FFMA2.
__global__ void __launch_bounds__(512)
k_l1(const float* __restrict__ W1, const int* __restrict__ cidx) {
    extern __shared__ __align__(16) float sm[];
    float* Ws  = sm;            // 84*256 = 21504
    float* C1s = sm + 21504;    // 2560
    float* E1s = sm + 24064;    // 256
    float* xs  = sm + 24320;    // 84*68 = 5712
    int*   cs  = (int*)(sm + 30032);  // 64 ints
    int tid = threadIdx.x, s = blockIdx.x;
    if (s == 0 && blockIdx.y == 0 && tid < 20) g_cursor[tid] = 0;  // next replay
    for (int i = tid; i < 84 * 256; i += 512) {
        int r = i >> 8, c = i & 255;
        int src = (r < 45) ? (128 + s * 45 + r) : (1028 + r - 45);
        Ws[i] = W1[src * 256 + c];
    }
    for (int i = tid; i < 2560; i += 512) C1s[i] = g_C1[i];
    if (tid < 256) E1s[tid] = g_E1[s * 256 + tid];
    __syncthreads();

    int cnt = g_hist[s], base = g_base[s];
    int st = cnt * blockIdx.y / 7, en = cnt * (blockIdx.y + 1) / 7;
    int lane = tid & 31, w = tid >> 5;
    int jq = w & 3, th = w >> 2;
    int j0 = jq * 64 + lane, j1 = j0 + 32, T0 = th * 16;
    ull e0 = f2pack(E1s[j0], E1s[j0]);
    ull e1 = f2pack(E1s[j1], E1s[j1]);

    for (int g0 = st; g0 < en; g0 += 64) {
        int n = min(64, en - g0);
        __syncthreads();
        if (tid < 64) cs[tid] = (tid < n) ? cidx[g_order[base + g0 + tid]] : 0;
        // staging: conflict-free transpose (lane = k, float4 of 4 tokens)
        for (int it = w; it < 48; it += 16) {
            int kc = it % 3, tc = it / 3;
            int k = kc * 32 + lane;
            if (k < 84) {
                int tb = tc * 4;
                float v[4];
#pragma unroll
                for (int i = 0; i < 4; i++) {
                    int t = tb + i;
                    v[i] = (t < n) ? g_feat[(size_t)g_order[base + g0 + t] * 88 + k] : 0.f;
                }
                *(float4*)&xs[k * 68 + tb] = make_float4(v[0], v[1], v[2], v[3]);
            }
        }
        __syncthreads();
        ull a0[8], a1[8];
#pragma unroll
        for (int u = 0; u < 8; u++) {
            int ca = cs[T0 + 2 * u], cb = cs[T0 + 2 * u + 1];
            a0[u] = fadd2(e0, f2pack(C1s[ca * 256 + j0], C1s[cb * 256 + j0]));
            a1[u] = fadd2(e1, f2pack(C1s[ca * 256 + j1], C1s[cb * 256 + j1]));
        }
#pragma unroll 4
        for (int k = 0; k < 84; k++) {
            float w0 = Ws[k * 256 + j0], w1 = Ws[k * 256 + j1];
            ull wd0 = f2pack(w0, w0), wd1 = f2pack(w1, w1);
            const ulonglong2* xr = (const ulonglong2*)&xs[k * 68 + T0];
            ulonglong2 xa = xr[0], xb = xr[1], xc = xr[2], xd = xr[3];
            a0[0] = ffma2(xa.x, wd0, a0[0]); a1[0] = ffma2(xa.x, wd1, a1[0]);
            a0[1] = ffma2(xa.y, wd0, a0[1]); a1[1] = ffma2(xa.y, wd1, a1[1]);
            a0[2] = ffma2(xb.x, wd0, a0[2]); a1[2] = ffma2(xb.x, wd1, a1[2]);
            a0[3] = ffma2(xb.y, wd0, a0[3]); a1[3] = ffma2(xb.y, wd1, a1[3]);
            a0[4] = ffma2(xc.x, wd0, a0[4]); a1[4] = ffma2(xc.x, wd1, a1[4]);
            a0[5] = ffma2(xc.y, wd0, a0[5]); a1[5] = ffma2(xc.y, wd1, a1[5]);
            a0[6] = ffma2(xd.x, wd0, a0[6]); a1[6] = ffma2(xd.x, wd1, a1[6]);
            a0[7] = ffma2(xd.y, wd0, a0[7]); a1[7] = ffma2(xd.y, wd1, a1[7]);
        }
#pragma unroll
        for (int u = 0; u < 8; u++) {
            int ta = T0 + 2 * u;
            if (ta < n) {
                int pa = (base + g0 + ta) * 256;
                float va0, vb0, va1, vb1;
                f2unpack(a0[u], va0, vb0);
                f2unpack(a1[u], va1, vb1);
                g_h1[pa + j0] = fmaxf(va0, 0.f);
                g_h1[pa + j1] = fmaxf(va1, 0.f);
                if (ta + 1 < n) {
                    g_h1[pa + 256 + j0] = fmaxf(vb0, 0.f);
                    g_h1[pa + 256 + j1] = fmaxf(vb1, 0.f);
                }
            }
        }
    }
}

// ---------------- layer 2: h2 = relu(h1 @ W2 + b2) ---------------------------
// 512 thr = 16 warps (2 j-half x 8 token-octets); K=256, J=128; 64 tok/group.
__global__ void __launch_bounds__(512)
k_l2(const float* __restrict__ W2, const float* __restrict__ b2, int ntok) {
    extern __shared__ __align__(16) float sm[];
    float* Ws = sm;            // 256*128 = 32768
    float* xs = sm + 32768;    // 256*68  = 17408
    int tid = threadIdx.x;
    if (blockIdx.x == 0 && tid < 20) g_hist[tid] = 0;  // next replay
    for (int i = tid * 4; i < 32768; i += 2048)
        *(float4*)&Ws[i] = *(const float4*)&W2[i];
    int lane = tid & 31, w = tid >> 5;
    int jh = w & 1, to = w >> 1;
    int j0 = jh * 64 + lane, j1 = j0 + 32, T0 = to * 8;
    ull bb0 = f2pack(b2[j0], b2[j0]), bb1 = f2pack(b2[j1], b2[j1]);
    int ngrp = (ntok + 63) >> 6;
    for (int u = blockIdx.x; u < ngrp; u += gridDim.x) {
        int t0 = u * 64;
        __syncthreads();
        // staging: lane = k, float4 of 4 tokens; coalesced LDG, conflict-free STS
        for (int it = w; it < 128; it += 16) {
            int kc = it & 7, tc = it >> 3;
            int k = kc * 32 + lane;
            int tb = t0 + tc * 4;
            float v0 = (tb + 0 < ntok) ? g_h1[(size_t)(tb + 0) * 256 + k] : 0.f;
            float v1 = (tb + 1 < ntok) ? g_h1[(size_t)(tb + 1) * 256 + k] : 0.f;
            float v2 = (tb + 2 < ntok) ? g_h1[(size_t)(tb + 2) * 256 + k] : 0.f;
            float v3 = (tb + 3 < ntok) ? g_h1[(size_t)(tb + 3) * 256 + k] : 0.f;
            *(float4*)&xs[k * 68 + tc * 4] = make_float4(v0, v1, v2, v3);
        }
        __syncthreads();
        ull a0[4], a1[4];
#pragma unroll
        for (int p = 0; p < 4; p++) { a0[p] = bb0; a1[p] = bb1; }
#pragma unroll 4
        for (int k = 0; k < 256; k++) {
            float w0 = Ws[k * 128 + j0], w1 = Ws[k * 128 + j1];
            ull wd0 = f2pack(w0, w0), wd1 = f2pack(w1, w1);
            const ulonglong2* xr = (const ulonglong2*)&xs[k * 68 + T0];
            ulonglong2 xa = xr[0], xb = xr[1];
            a0[0] = ffma2(xa.x, wd0, a0[0]); a1[0] = ffma2(xa.x, wd1, a1[0]);
            a0[1] = ffma2(xa.y, wd0, a0[1]); a1[1] = ffma2(xa.y, wd1, a1[1]);
            a0[2] = ffma2(xb.x, wd0, a0[2]); a1[2] = ffma2(xb.x, wd1, a1[2]);
            a0[3] = ffma2(xb.y, wd0, a0[3]); a1[3] = ffma2(xb.y, wd1, a1[3]);
        }
#pragma unroll
        for (int p = 0; p < 4; p++) {
            int ta = t0 + T0 + 2 * p;
            if (ta < ntok) {
                float va0, vb0, va1, vb1;
                f2unpack(a0[p], va0, vb0);
                f2unpack(a1[p], va1, vb1);
                g_h2[ta * 128 + j0] = fmaxf(va0, 0.f);
                g_h2[ta * 128 + j1] = fmaxf(va1, 0.f);
                if (ta + 1 < ntok) {
                    g_h2[(ta + 1) * 128 + j0] = fmaxf(vb0, 0.f);
                    g_h2[(ta + 1) * 128 + j1] = fmaxf(vb1, 0.f);
                }
            }
        }
    }
}

// ---------------- layers 3+4 fused ------------------------------------------
// 512 thr = 16 warps (2 j-half x 8 token-octets); 64 tokens/group.
__global__ void __launch_bounds__(512)
k_l34(const float* __restrict__ W3, const float* __restrict__ b3,
      const float* __restrict__ W4, const float* __restrict__ b4,
      float* __restrict__ out, int ntok) {
    extern __shared__ __align__(16) float sm[];
    float* W3s = sm;              // 16384
    float* W4s = sm + 16384;      // 16384
    float* xs  = sm + 32768;      // 128*68 = 8704
    float* hs  = sm + 41472;      // 128*68 = 8704
    int*   os  = (int*)(sm + 50176);  // 64 ints
    int tid = threadIdx.x;
    for (int i = tid * 4; i < 16384; i += 2048) {
        *(float4*)&W3s[i] = *(const float4*)&W3[i];
        *(float4*)&W4s[i] = *(const float4*)&W4[i];
    }
    int lane = tid & 31, w = tid >> 5;
    int jh = w & 1, to = w >> 1;
    int j0 = jh * 64 + lane, j1 = j0 + 32, T0 = to * 8;
    ull b30 = f2pack(b3[j0], b3[j0]), b31 = f2pack(b3[j1], b3[j1]);
    ull b40 = f2pack(b4[j0], b4[j0]), b41 = f2pack(b4[j1], b4[j1]);
    int ngrp = (ntok + 63) >> 6;
    for (int u = blockIdx.x; u < ngrp; u += gridDim.x) {
        int t0 = u * 64;
        __syncthreads();
        if (tid < 64) os[tid] = (t0 + tid < ntok) ? g_order[t0 + tid] : 0;
        for (int it = w; it < 64; it += 16) {
            int kc = it & 3, tc = it >> 2;
            int k = kc * 32 + lane;
            int tb = t0 + tc * 4;
            float v0 = (tb + 0 < ntok) ? g_h2[(size_t)(tb + 0) * 128 + k] : 0.f;
            float v1 = (tb + 1 < ntok) ? g_h2[(size_t)(tb + 1) * 128 + k] : 0.f;
            float v2 = (tb + 2 < ntok) ? g_h2[(size_t)(tb + 2) * 128 + k] : 0.f;
            float v3 = (tb + 3 < ntok) ? g_h2[(size_t)(tb + 3) * 128 + k] : 0.f;
            *(float4*)&xs[k * 68 + tc * 4] = make_float4(v0, v1, v2, v3);
        }
        __syncthreads();
        // ---- L3 ----
        ull a0[4], a1[4];
#pragma unroll
        for (int p = 0; p < 4; p++) { a0[p] = b30; a1[p] = b31; }
#pragma unroll 4
        for (int k = 0; k < 128; k++) {
            float w0 = W3s[k * 128 + j0], w1 = W3s[k * 128 + j1];
            ull wd0 = f2pack(w0, w0), wd1 = f2pack(w1, w1);
            const ulonglong2* xr = (const ulonglong2*)&xs[k * 68 + T0];
            ulonglong2 xa = xr[0], xb = xr[1];
            a0[0] = ffma2(xa.x, wd0, a0[0]); a1[0] = ffma2(xa.x, wd1, a1[0]);
            a0[1] = ffma2(xa.y, wd0, a0[1]); a1[1] = ffma2(xa.y, wd1, a1[1]);
            a0[2] = ffma2(xb.x, wd0, a0[2]); a1[2] = ffma2(xb.x, wd1, a1[2]);
            a0[3] = ffma2(xb.y, wd0, a0[3]); a1[3] = ffma2(xb.y, wd1, a1[3]);
        }
#pragma unroll
        for (int p = 0; p < 4; p++) {
            float va0, vb0, va1, vb1;
            f2unpack(a0[p], va0, vb0);
            f2unpack(a1[p], va1, vb1);
            *(ull*)&hs[j0 * 68 + T0 + 2 * p] = f2pack(fmaxf(va0, 0.f), fmaxf(vb0, 0.f));
            *(ull*)&hs[j1 * 68 + T0 + 2 * p] = f2pack(fmaxf(va1, 0.f), fmaxf(vb1, 0.f));
        }
        __syncthreads();
        // ---- L4 ----
#pragma unroll
        for (int p = 0; p < 4; p++) { a0[p] = b40; a1[p] = b41; }
#pragma unroll 4
        for (int k = 0; k < 128; k++) {
            float w0 = W4s[k * 128 + j0], w1 = W4s[k * 128 + j1];
            ull wd0 = f2pack(w0, w0), wd1 = f2pack(w1, w1);
            const ulonglong2* xr = (const ulonglong2*)&hs[k * 68 + T0];
            ulonglong2 xa = xr[0], xb = xr[1];
            a0[0] = ffma2(xa.x, wd0, a0[0]); a1[0] = ffma2(xa.x, wd1, a1[0]);
            a0[1] = ffma2(xa.y, wd0, a0[1]); a1[1] = ffma2(xa.y, wd1, a1[1]);
            a0[2] = ffma2(xb.x, wd0, a0[2]); a1[2] = ffma2(xb.x, wd1, a1[2]);
            a0[3] = ffma2(xb.y, wd0, a0[3]); a1[3] = ffma2(xb.y, wd1, a1[3]);
        }
#pragma unroll
        for (int p = 0; p < 4; p++) {
            int ta = T0 + 2 * p;
            if (t0 + ta < ntok) {
                float va0, vb0, va1, vb1;
                f2unpack(a0[p], va0, vb0);
                f2unpack(a1[p], va1, vb1);
                int oa = os[ta];
                out[oa * 128 + j0] = va0;
                out[oa * 128 + j1] = va1;
                if (t0 + ta + 1 < ntok) {
                    int ob = os[ta + 1];
                    out[ob * 128 + j0] = vb0;
                    out[ob * 128 + j1] = vb1;
                }
            }
        }
    }
}

// ---------------- launch ----------------------------------------------------
extern "C" void kernel_launch(void* const* d_in, const int* in_sizes, int n_in,
                              void* d_out, int out_size) {
    const int*   seq    = (const int*)  d_in[0];
    const float* xyz    = (const float*)d_in[1];
    const float* dih    = (const float*)d_in[2];
    const int*   cidx   = (const int*)  d_in[3];
    const float* ori    = (const float*)d_in[4];
    /* d_in[5] = atom_mask : unused by reference */
    const float* aa_emb = (const float*)d_in[6];
    const float* ch_emb = (const float*)d_in[7];
    const float* W1 = (const float*)d_in[8];
    const float* b1 = (const float*)d_in[9];
    const float* W2 = (const float*)d_in[10];
    const float* b2 = (const float*)d_in[11];
    const float* W3 = (const float*)d_in[12];
    const float* b3 = (const float*)d_in[13];
    const float* W4 = (const float*)d_in[14];
    const float* b4 = (const float*)d_in[15];
    float* out = (float*)d_out;
    int ntok = in_sizes[0];
    if (ntok > MAXTOK) ntok = MAXTOK;

    int nfeatblk = (ntok + 255) / 256;
    const int SMEM1  = (30032 + 64) * 4;              // 120384 B
    const int SMEM2  = (32768 + 17408) * 4;           // 200704 B
    const int SMEM34 = (50176 + 64) * 4;              // 200960 B
    cudaFuncSetAttribute(k_l1,  cudaFuncAttributeMaxDynamicSharedMemorySize, SMEM1);
    cudaFuncSetAttribute(k_l2,  cudaFuncAttributeMaxDynamicSharedMemorySize, SMEM2);
    cudaFuncSetAttribute(k_l34, cudaFuncAttributeMaxDynamicSharedMemorySize, SMEM34);

    k_setup<<<30 + nfeatblk, 256>>>(aa_emb, ch_emb, W1, b1, xyz, ori, dih, seq,
                                    ntok, nfeatblk);
    k_scatter<<<(ntok + 255) / 256, 256>>>(seq, ntok);
    k_l1<<<dim3(20, 7), 512, SMEM1>>>(W1, cidx);
    k_l2<<<128, 512, SMEM2>>>(W2, b2, ntok);
    k_l34<<<128, 512, SMEM34>>>(W3, b3, W4, b4, out, ntok);
}

// round 7
// speedup vs baseline: 1.0653x; 1.0648x over previous
#include <cuda_runtime.h>

#define MAXTOK 16384

// ---------------- scratch (device globals; no allocation allowed) ----------
__device__ float g_feat[MAXTOK * 88];   // [tok][88]: 0..44 coord, 45..83 dihedral
__device__ float g_h1[MAXTOK * 256];    // sorted-token order
__device__ float g_h2[MAXTOK * 128];    // sorted-token order
__device__ float g_E1[20 * 256];
__device__ float g_C1[10 * 256];
__device__ int g_hist[20];
__device__ int g_base[20];
__device__ int g_cursor[20];
__device__ int g_order[MAXTOK];         // sorted pos -> original token
__device__ int g_done;

typedef unsigned long long ull;

static __device__ __forceinline__ ull f2pack(float lo, float hi) {
    ull r; asm("mov.b64 %0,{%1,%2};" : "=l"(r) : "f"(lo), "f"(hi)); return r;
}
static __device__ __forceinline__ void f2unpack(ull v, float& lo, float& hi) {
    asm("mov.b64 {%0,%1},%2;" : "=f"(lo), "=f"(hi) : "l"(v));
}
static __device__ __forceinline__ ull ffma2(ull a, ull b, ull c) {
    ull d; asm("fma.rn.f32x2 %0,%1,%2,%3;" : "=l"(d) : "l"(a), "l"(b), "l"(c)); return d;
}
static __device__ __forceinline__ ull fadd2(ull a, ull b) {
    ull d; asm("add.rn.f32x2 %0,%1,%2;" : "=l"(d) : "l"(a), "l"(b)); return d;
}

// ---------------- setup: E1/C1 tables + per-token features + hist + scan ----
__global__ void __launch_bounds__(256)
k_setup(const float* __restrict__ aa_emb, const float* __restrict__ ch_emb,
        const float* __restrict__ W1, const float* __restrict__ b1,
        const float* __restrict__ xyz, const float* __restrict__ ori,
        const float* __restrict__ dih, const int* __restrict__ seq,
        int ntok, int nfeatblk) {
    int b = blockIdx.x, tid = threadIdx.x;
    if (b < 30) {  // precompute E1 / C1
        int j = tid;
        if (b < 20) {
            float acc = b1[j];
#pragma unroll 8
            for (int k = 0; k < 128; k++) acc += aa_emb[b * 128 + k] * W1[k * 256 + j];
            g_E1[b * 256 + j] = acc;
        } else {
            int c = b - 20;
            float acc = 0.f;
            if (c != 0) {
#pragma unroll 8
                for (int k = 0; k < 128; k++)
                    acc += ch_emb[c * 128 + k] * W1[(1067 + k) * 256 + j];
            }
            g_C1[c * 256 + j] = acc;
        }
        return;
    }
    int t = (b - 30) * 256 + tid;
    if (t < ntok) {
        const float* X = xyz + t * 45;
        float ca0 = X[3], ca1 = X[4], ca2 = X[5];   // CA_IDX = 1
        float o[9];
#pragma unroll
        for (int i = 0; i < 9; i++) o[i] = ori[t * 9 + i];
        float* F = g_feat + t * 88;
#pragma unroll
        for (int a = 0; a < 15; a++) {
            float rx = X[a * 3 + 0] - ca0;
            float ry = X[a * 3 + 1] - ca1;
            float rz = X[a * 3 + 2] - ca2;
#pragma unroll
            for (int i = 0; i < 3; i++)  // O^T @ rel
                F[a * 3 + i] = o[i] * rx + o[3 + i] * ry + o[6 + i] * rz;
        }
        const float fb[6] = {1.f, 2.f, 3.f, 1.f, 0.5f, 1.f / 3.f};
#pragma unroll
        for (int d = 0; d < 3; d++) {
            float x = dih[t * 3 + d];
            int bo = 45 + d * 13;
            F[bo] = x;
#pragma unroll
            for (int u = 0; u < 6; u++) {
                F[bo + 1 + u] = sinf(fb[u] * x);
                F[bo + 7 + u] = cosf(fb[u] * x);
            }
        }
        atomicAdd(&g_hist[seq[t]], 1);
    }
    __syncthreads();
    if (tid == 0) {
        __threadfence();
        if (atomicAdd(&g_done, 1) == nfeatblk - 1) {  // last feat block: scan
            __threadfence();
            int s = 0;
            for (int i = 0; i < 20; i++) {
                int h = atomicAdd(&g_hist[i], 0);
                g_base[i] = s; s += h;
            }
            atomicExch(&g_done, 0);  // reset for next replay
        }
    }
}

// ---------------- block-aggregated counting-sort scatter ---------------------
__global__ void __launch_bounds__(256)
k_scatter(const int* __restrict__ seq, int ntok) {
    __shared__ int lh[20], lb[20], lc[20];
    int tid = threadIdx.x;
    if (tid < 20) { lh[tid] = 0; lc[tid] = 0; }
    __syncthreads();
    int t = blockIdx.x * 256 + tid;
    int s = -1;
    if (t < ntok) { s = seq[t]; atomicAdd(&lh[s], 1); }
    __syncthreads();
    if (tid < 20 && lh[tid] > 0) lb[tid] = atomicAdd(&g_cursor[tid], lh[tid]);
    __syncthreads();
    if (t < ntok) {
        int p = atomicAdd(&lc[s], 1);
        g_order[g_base[s] + lb[s] + p] = t;
    }
}

// ---------------- layer 1 (dense+coord merged), grouped by aa type -----------
// grid (20, 14); 512 thr, 2 blocks/SM; K=84 (2 chunks of 42), 32 tok/group.
// 16 warps = 4 j-quarters x 4 token-octets.
__global__ void __launch_bounds__(512, 2)
k_l1(const float* __restrict__ W1, const int* __restrict__ cidx) {
    extern __shared__ __align__(16) float sm[];
    float* Wc  = sm;            // 42*256 = 10752
    float* C1s = sm + 10752;    // 2560
    float* E1s = sm + 13312;    // 256
    float* xs  = sm + 13568;    // 84*36 = 3024
    int*   cs  = (int*)(sm + 16592);  // 32 ints
    int tid = threadIdx.x, s = blockIdx.x;
    if (s == 0 && blockIdx.y == 0 && tid < 20) g_cursor[tid] = 0;  // next replay
    for (int i = tid; i < 2560; i += 512) C1s[i] = g_C1[i];
    if (tid < 256) E1s[tid] = g_E1[s * 256 + tid];

    int cnt = g_hist[s], base = g_base[s];
    int st = cnt * blockIdx.y / 14, en = cnt * (blockIdx.y + 1) / 14;
    int lane = tid & 31, w_ = tid >> 5;
    int jq = w_ & 3, th = w_ >> 2;
    int j0 = jq * 64 + lane, j1 = j0 + 32, T0 = th * 8;
    __syncthreads();  // C1s/E1s ready
    ull e0 = f2pack(E1s[j0], E1s[j0]);
    ull e1 = f2pack(E1s[j1], E1s[j1]);

    for (int g0 = st; g0 < en; g0 += 32) {
        int n = min(32, en - g0);
        __syncthreads();  // prev group's xs/cs/Wc readers done
        if (tid < 32) cs[tid] = (tid < n) ? cidx[g_order[base + g0 + tid]] : 0;
        // stage features: lane = k, float4 of 4 tokens (conflict-free)
        for (int it = w_; it < 24; it += 16) {
            int kc = it % 3, tc = it / 3;
            int k = kc * 32 + lane;
            if (k < 84) {
                int tb = tc * 4;
                float v[4];
#pragma unroll
                for (int i = 0; i < 4; i++) {
                    int t = tb + i;
                    v[i] = (t < n) ? g_feat[(size_t)g_order[base + g0 + t] * 88 + k] : 0.f;
                }
                *(float4*)&xs[k * 36 + tb] = make_float4(v[0], v[1], v[2], v[3]);
            }
        }
        // stage W chunk 0 (rows 0..41)
        for (int i = tid * 4; i < 10752; i += 2048) {
            int r = i >> 8, c = i & 255;
            int src = (r < 45) ? (128 + s * 45 + r) : (1028 + r - 45);
            *(float4*)&Wc[i] = *(const float4*)&W1[src * 256 + c];
        }
        __syncthreads();
        ull a0[4], a1[4];
#pragma unroll
        for (int u = 0; u < 4; u++) {
            int ca = cs[T0 + 2 * u], cb = cs[T0 + 2 * u + 1];
            a0[u] = fadd2(e0, f2pack(C1s[ca * 256 + j0], C1s[cb * 256 + j0]));
            a1[u] = fadd2(e1, f2pack(C1s[ca * 256 + j1], C1s[cb * 256 + j1]));
        }
#pragma unroll
        for (int c = 0; c < 2; c++) {
            if (c == 1) {  // restage W chunk 1 (rows 42..83)
                __syncthreads();
                for (int i = tid * 4; i < 10752; i += 2048) {
                    int r = 42 + (i >> 8), cc2 = i & 255;
                    int src = (r < 45) ? (128 + s * 45 + r) : (1028 + r - 45);
                    *(float4*)&Wc[i] = *(const float4*)&W1[src * 256 + cc2];
                }
                __syncthreads();
            }
#pragma unroll 4
            for (int kk = 0; kk < 42; kk++) {
                int k = c * 42 + kk;
                float w0 = Wc[kk * 256 + j0], w1 = Wc[kk * 256 + j1];
                ull wd0 = f2pack(w0, w0), wd1 = f2pack(w1, w1);
                const ulonglong2* xr = (const ulonglong2*)&xs[k * 36 + T0];
                ulonglong2 xa = xr[0], xb = xr[1];
                a0[0] = ffma2(xa.x, wd0, a0[0]); a1[0] = ffma2(xa.x, wd1, a1[0]);
                a0[1] = ffma2(xa.y, wd0, a0[1]); a1[1] = ffma2(xa.y, wd1, a1[1]);
                a0[2] = ffma2(xb.x, wd0, a0[2]); a1[2] = ffma2(xb.x, wd1, a1[2]);
                a0[3] = ffma2(xb.y, wd0, a0[3]); a1[3] = ffma2(xb.y, wd1, a1[3]);
            }
        }
#pragma unroll
        for (int u = 0; u < 4; u++) {
            int ta = T0 + 2 * u;
            if (ta < n) {
                int pa = (base + g0 + ta) * 256;
                float va0, vb0, va1, vb1;
                f2unpack(a0[u], va0, vb0);
                f2unpack(a1[u], va1, vb1);
                g_h1[pa + j0] = fmaxf(va0, 0.f);
                g_h1[pa + j1] = fmaxf(va1, 0.f);
                if (ta + 1 < n) {
                    g_h1[pa + 256 + j0] = fmaxf(vb0, 0.f);
                    g_h1[pa + 256 + j1] = fmaxf(vb1, 0.f);
                }
            }
        }
    }
}

// ---------------- layer 2: h2 = relu(h1 @ W2 + b2) ---------------------------
// grid 256 (1 group of 64 tok per block); 512 thr, 2 blocks/SM.
// W2 staged in 4 chunks of 64 k-rows (32KB), single-buffered.
__global__ void __launch_bounds__(512, 2)
k_l2(const float* __restrict__ W2, const float* __restrict__ b2, int ntok) {
    extern __shared__ __align__(16) float sm[];
    float* xs = sm;            // 256*68 = 17408
    float* Wc = sm + 17408;    // 64*128 = 8192
    int tid = threadIdx.x;
    if (blockIdx.x == 0 && tid < 20) g_hist[tid] = 0;  // next replay
    int lane = tid & 31, w_ = tid >> 5;
    int jh = w_ & 1, to = w_ >> 1;
    int j0 = jh * 64 + lane, j1 = j0 + 32, T0 = to * 8;
    int t0 = blockIdx.x * 64;
    // stage xs (all 256 k): lane = k, float4 of 4 tokens (conflict-free)
    for (int it = w_; it < 128; it += 16) {
        int kc = it & 7, tc = it >> 3;
        int k = kc * 32 + lane;
        int tb = t0 + tc * 4;
        float v0 = (tb + 0 < ntok) ? g_h1[(size_t)(tb + 0) * 256 + k] : 0.f;
        float v1 = (tb + 1 < ntok) ? g_h1[(size_t)(tb + 1) * 256 + k] : 0.f;
        float v2 = (tb + 2 < ntok) ? g_h1[(size_t)(tb + 2) * 256 + k] : 0.f;
        float v3 = (tb + 3 < ntok) ? g_h1[(size_t)(tb + 3) * 256 + k] : 0.f;
        *(float4*)&xs[k * 68 + tc * 4] = make_float4(v0, v1, v2, v3);
    }
    // stage W chunk 0
    for (int i = tid * 4; i < 8192; i += 2048)
        *(float4*)&Wc[i] = *(const float4*)&W2[i];
    __syncthreads();

    ull bb0 = f2pack(b2[j0], b2[j0]), bb1 = f2pack(b2[j1], b2[j1]);
    ull a0[4], a1[4];
#pragma unroll
    for (int p = 0; p < 4; p++) { a0[p] = bb0; a1[p] = bb1; }
#pragma unroll
    for (int c = 0; c < 4; c++) {
        if (c > 0) {
            __syncthreads();
            for (int i = tid * 4; i < 8192; i += 2048)
                *(float4*)&Wc[i] = *(const float4*)&W2[c * 8192 + i];
            __syncthreads();
        }
#pragma unroll 4
        for (int kk = 0; kk < 64; kk++) {
            int k = c * 64 + kk;
            float w0 = Wc[kk * 128 + j0], w1 = Wc[kk * 128 + j1];
            ull wd0 = f2pack(w0, w0), wd1 = f2pack(w1, w1);
            const ulonglong2* xr = (const ulonglong2*)&xs[k * 68 + T0];
            ulonglong2 xa = xr[0], xb = xr[1];
            a0[0] = ffma2(xa.x, wd0, a0[0]); a1[0] = ffma2(xa.x, wd1, a1[0]);
            a0[1] = ffma2(xa.y, wd0, a0[1]); a1[1] = ffma2(xa.y, wd1, a1[1]);
            a0[2] = ffma2(xb.x, wd0, a0[2]); a1[2] = ffma2(xb.x, wd1, a1[2]);
            a0[3] = ffma2(xb.y, wd0, a0[3]); a1[3] = ffma2(xb.y, wd1, a1[3]);
        }
    }
#pragma unroll
    for (int p = 0; p < 4; p++) {
        int ta = t0 + T0 + 2 * p;
        if (ta < ntok) {
            float va0, vb0, va1, vb1;
            f2unpack(a0[p], va0, vb0);
            f2unpack(a1[p], va1, vb1);
            g_h2[ta * 128 + j0] = fmaxf(va0, 0.f);
            g_h2[ta * 128 + j1] = fmaxf(va1, 0.f);
            if (ta + 1 < ntok) {
                g_h2[(ta + 1) * 128 + j0] = fmaxf(vb0, 0.f);
                g_h2[(ta + 1) * 128 + j1] = fmaxf(vb1, 0.f);
            }
        }
    }
}

// ---------------- layers 3+4 fused ------------------------------------------
// grid 256 (1 group of 64 tok per block); 512 thr, 2 blocks/SM.
// W3 then W4 staged in 2 chunks each (32KB), single-buffered.
__global__ void __launch_bounds__(512, 2)
k_l34(const float* __restrict__ W3, const float* __restrict__ b3,
      const float* __restrict__ W4, const float* __restrict__ b4,
      float* __restrict__ out, int ntok) {
    extern __shared__ __align__(16) float sm[];
    float* xs = sm;               // 128*68 = 8704
    float* hs = sm + 8704;        // 128*68 = 8704
    float* Wc = sm + 17408;       // 64*128 = 8192
    int*   os = (int*)(sm + 25600);  // 64 ints
    int tid = threadIdx.x;
    int lane = tid & 31, w_ = tid >> 5;
    int jh = w_ & 1, to = w_ >> 1;
    int j0 = jh * 64 + lane, j1 = j0 + 32, T0 = to * 8;
    int t0 = blockIdx.x * 64;
    if (tid < 64) os[tid] = (t0 + tid < ntok) ? g_order[t0 + tid] : 0;
    for (int it = w_; it < 64; it += 16) {
        int kc = it & 3, tc = it >> 2;
        int k = kc * 32 + lane;
        int tb = t0 + tc * 4;
        float v0 = (tb + 0 < ntok) ? g_h2[(size_t)(tb + 0) * 128 + k] : 0.f;
        float v1 = (tb + 1 < ntok) ? g_h2[(size_t)(tb + 1) * 128 + k] : 0.f;
        float v2 = (tb + 2 < ntok) ? g_h2[(size_t)(tb + 2) * 128 + k] : 0.f;
        float v3 = (tb + 3 < ntok) ? g_h2[(size_t)(tb + 3) * 128 + k] : 0.f;
        *(float4*)&xs[k * 68 + tc * 4] = make_float4(v0, v1, v2, v3);
    }
    for (int i = tid * 4; i < 8192; i += 2048)
        *(float4*)&Wc[i] = *(const float4*)&W3[i];
    __syncthreads();

    ull b30 = f2pack(b3[j0], b3[j0]), b31 = f2pack(b3[j1], b3[j1]);
    ull b40 = f2pack(b4[j0], b4[j0]), b41 = f2pack(b4[j1], b4[j1]);
    ull a0[4], a1[4];
    // ---- L3 ----
#pragma unroll
    for (int p = 0; p < 4; p++) { a0[p] = b30; a1[p] = b31; }
#pragma unroll
    for (int c = 0; c < 2; c++) {
        if (c == 1) {
            __syncthreads();
            for (int i = tid * 4; i < 8192; i += 2048)
                *(float4*)&Wc[i] = *(const float4*)&W3[8192 + i];
            __syncthreads();
        }
#pragma unroll 4
        for (int kk = 0; kk < 64; kk++) {
            int k = c * 64 + kk;
            float w0 = Wc[kk * 128 + j0], w1 = Wc[kk * 128 + j1];
            ull wd0 = f2pack(w0, w0), wd1 = f2pack(w1, w1);
            const ulonglong2* xr = (const ulonglong2*)&xs[k * 68 + T0];
            ulonglong2 xa = xr[0], xb = xr[1];
            a0[0] = ffma2(xa.x, wd0, a0[0]); a1[0] = ffma2(xa.x, wd1, a1[0]);
            a0[1] = ffma2(xa.y, wd0, a0[1]); a1[1] = ffma2(xa.y, wd1, a1[1]);
            a0[2] = ffma2(xb.x, wd0, a0[2]); a1[2] = ffma2(xb.x, wd1, a1[2]);
            a0[3] = ffma2(xb.y, wd0, a0[3]); a1[3] = ffma2(xb.y, wd1, a1[3]);
        }
    }
    // relu -> hs (token-major rows, same layout as xs)
#pragma unroll
    for (int p = 0; p < 4; p++) {
        float va0, vb0, va1, vb1;
        f2unpack(a0[p], va0, vb0);
        f2unpack(a1[p], va1, vb1);
        *(ull*)&hs[j0 * 68 + T0 + 2 * p] = f2pack(fmaxf(va0, 0.f), fmaxf(vb0, 0.f));
        *(ull*)&hs[j1 * 68 + T0 + 2 * p] = f2pack(fmaxf(va1, 0.f), fmaxf(vb1, 0.f));
    }
    // ---- L4 ----
#pragma unroll
    for (int p = 0; p < 4; p++) { a0[p] = b40; a1[p] = b41; }
#pragma unroll
    for (int c = 0; c < 2; c++) {
        __syncthreads();  // c=0: hs ready + W3 readers done; c=1: prev chunk done
        for (int i = tid * 4; i < 8192; i += 2048)
            *(float4*)&Wc[i] = *(const float4*)&W4[c * 8192 + i];
        __syncthreads();
#pragma unroll 4
        for (int kk = 0; kk < 64; kk++) {
            int k = c * 64 + kk;
            float w0 = Wc[kk * 128 + j0], w1 = Wc[kk * 128 + j1];
            ull wd0 = f2pack(w0, w0), wd1 = f2pack(w1, w1);
            const ulonglong2* xr = (const ulonglong2*)&hs[k * 68 + T0];
            ulonglong2 xa = xr[0], xb = xr[1];
            a0[0] = ffma2(xa.x, wd0, a0[0]); a1[0] = ffma2(xa.x, wd1, a1[0]);
            a0[1] = ffma2(xa.y, wd0, a0[1]); a1[1] = ffma2(xa.y, wd1, a1[1]);
            a0[2] = ffma2(xb.x, wd0, a0[2]); a1[2] = ffma2(xb.x, wd1, a1[2]);
            a0[3] = ffma2(xb.y, wd0, a0[3]); a1[3] = ffma2(xb.y, wd1, a1[3]);
        }
    }
#pragma unroll
    for (int p = 0; p < 4; p++) {
        int ta = T0 + 2 * p;
        if (t0 + ta < ntok) {
            float va0, vb0, va1, vb1;
            f2unpack(a0[p], va0, vb0);
            f2unpack(a1[p], va1, vb1);
            int oa = os[ta];
            out[oa * 128 + j0] = va0;
            out[oa * 128 + j1] = va1;
            if (t0 + ta + 1 < ntok) {
                int ob = os[ta + 1];
                out[ob * 128 + j0] = vb0;
                out[ob * 128 + j1] = vb1;
            }
        }
    }
}

// ---------------- launch ----------------------------------------------------
extern "C" void kernel_launch(void* const* d_in, const int* in_sizes, int n_in,
                              void* d_out, int out_size) {
    const int*   seq    = (const int*)  d_in[0];
    const float* xyz    = (const float*)d_in[1];
    const float* dih    = (const float*)d_in[2];
    const int*   cidx   = (const int*)  d_in[3];
    const float* ori    = (const float*)d_in[4];
    /* d_in[5] = atom_mask : unused by reference */
    const float* aa_emb = (const float*)d_in[6];
    const float* ch_emb = (const float*)d_in[7];
    const float* W1 = (const float*)d_in[8];
    const float* b1 = (const float*)d_in[9];
    const float* W2 = (const float*)d_in[10];
    const float* b2 = (const float*)d_in[11];
    const float* W3 = (const float*)d_in[12];
    const float* b3 = (const float*)d_in[13];
    const float* W4 = (const float*)d_in[14];
    const float* b4 = (const float*)d_in[15];
    float* out = (float*)d_out;
    int ntok = in_sizes[0];
    if (ntok > MAXTOK) ntok = MAXTOK;

    int nfeatblk = (ntok + 255) / 256;
    int ngrp = (ntok + 63) / 64;
    const int SMEM1  = (16592 + 32) * 4;     // 66496 B  -> 2 blocks/SM
    const int SMEM2  = (17408 + 8192) * 4;   // 102400 B -> 2 blocks/SM
    const int SMEM34 = (25600 + 64) * 4;     // 102656 B -> 2 blocks/SM
    cudaFuncSetAttribute(k_l1,  cudaFuncAttributeMaxDynamicSharedMemorySize, SMEM1);
    cudaFuncSetAttribute(k_l2,  cudaFuncAttributeMaxDynamicSharedMemorySize, SMEM2);
    cudaFuncSetAttribute(k_l34, cudaFuncAttributeMaxDynamicSharedMemorySize, SMEM34);

    k_setup<<<30 + nfeatblk, 256>>>(aa_emb, ch_emb, W1, b1, xyz, ori, dih, seq,
                                    ntok, nfeatblk);
    k_scatter<<<(ntok + 255) / 256, 256>>>(seq, ntok);
    k_l1<<<dim3(20, 14), 512, SMEM1>>>(W1, cidx);
    k_l2<<<ngrp, 512, SMEM2>>>(W2, b2, ntok);
    k_l34<<<ngrp, 512, SMEM34>>>(W3, b3, W4, b4, out, ntok);
}

// round 11
// speedup vs baseline: 1.5169x; 1.4239x over previous
#include <cuda_runtime.h>
#include <cuda_bf16.h>
#include <cstdint>

#define MAXTOK 16384

// ---------------- scratch (device globals; no allocation allowed) ----------
__device__ float g_feat[MAXTOK * 88];   // [tok][88]: 0..44 coord, 45..83 dihedral
__device__ float g_h1[MAXTOK * 256];    // sorted-token order (fp32)
__device__ float g_E1[20 * 256];
__device__ float g_C1[10 * 256];
__device__ int g_hist[20];
__device__ int g_base[20];
__device__ int g_cursor[20];
__device__ int g_order[MAXTOK];         // sorted pos -> original token
__device__ int g_done;

typedef unsigned long long ull;

static __device__ __forceinline__ ull f2pack(float lo, float hi) {
    ull r; asm("mov.b64 %0,{%1,%2};" : "=l"(r) : "f"(lo), "f"(hi)); return r;
}
static __device__ __forceinline__ void f2unpack(ull v, float& lo, float& hi) {
    asm("mov.b64 {%0,%1},%2;" : "=f"(lo), "=f"(hi) : "l"(v));
}
static __device__ __forceinline__ ull ffma2(ull a, ull b, ull c) {
    ull d; asm("fma.rn.f32x2 %0,%1,%2,%3;" : "=l"(d) : "l"(a), "l"(b), "l"(c)); return d;
}
static __device__ __forceinline__ ull fadd2(ull a, ull b) {
    ull d; asm("add.rn.f32x2 %0,%1,%2;" : "=l"(d) : "l"(a), "l"(b)); return d;
}

// ---------------- setup: E1/C1 tables + per-token features + hist + scan ----
__global__ void __launch_bounds__(256)
k_setup(const float* __restrict__ aa_emb, const float* __restrict__ ch_emb,
        const float* __restrict__ W1, const float* __restrict__ b1,
        const float* __restrict__ xyz, const float* __restrict__ ori,
        const float* __restrict__ dih, const int* __restrict__ seq,
        int ntok, int nfeatblk) {
    int b = blockIdx.x, tid = threadIdx.x;
    if (b < 30) {
        int j = tid;
        if (b < 20) {
            float acc = b1[j];
#pragma unroll 8
            for (int k = 0; k < 128; k++) acc += aa_emb[b * 128 + k] * W1[k * 256 + j];
            g_E1[b * 256 + j] = acc;
        } else {
            int c = b - 20;
            float acc = 0.f;
            if (c != 0) {
#pragma unroll 8
                for (int k = 0; k < 128; k++)
                    acc += ch_emb[c * 128 + k] * W1[(1067 + k) * 256 + j];
            }
            g_C1[c * 256 + j] = acc;
        }
        return;
    }
    int t = (b - 30) * 256 + tid;
    if (t < ntok) {
        const float* X = xyz + t * 45;
        float ca0 = X[3], ca1 = X[4], ca2 = X[5];   // CA_IDX = 1
        float o[9];
#pragma unroll
        for (int i = 0; i < 9; i++) o[i] = ori[t * 9 + i];
        float* F = g_feat + t * 88;
#pragma unroll
        for (int a = 0; a < 15; a++) {
            float rx = X[a * 3 + 0] - ca0;
            float ry = X[a * 3 + 1] - ca1;
            float rz = X[a * 3 + 2] - ca2;
#pragma unroll
            for (int i = 0; i < 3; i++)
                F[a * 3 + i] = o[i] * rx + o[3 + i] * ry + o[6 + i] * rz;
        }
        const float fb[6] = {1.f, 2.f, 3.f, 1.f, 0.5f, 1.f / 3.f};
#pragma unroll
        for (int d = 0; d < 3; d++) {
            float x = dih[t * 3 + d];
            int bo = 45 + d * 13;
            F[bo] = x;
#pragma unroll
            for (int u = 0; u < 6; u++) {
                F[bo + 1 + u] = sinf(fb[u] * x);
                F[bo + 7 + u] = cosf(fb[u] * x);
            }
        }
        atomicAdd(&g_hist[seq[t]], 1);
    }
    __syncthreads();
    if (tid == 0) {
        __threadfence();
        if (atomicAdd(&g_done, 1) == nfeatblk - 1) {
            __threadfence();
            int s = 0;
            for (int i = 0; i < 20; i++) {
                int h = atomicAdd(&g_hist[i], 0);
                g_base[i] = s; s += h;
            }
            atomicExch(&g_done, 0);
        }
    }
}

// ---------------- block-aggregated counting-sort scatter ---------------------
__global__ void __launch_bounds__(256)
k_scatter(const int* __restrict__ seq, int ntok) {
    __shared__ int lh[20], lb[20], lc[20];
    int tid = threadIdx.x;
    if (tid < 20) { lh[tid] = 0; lc[tid] = 0; }
    __syncthreads();
    int t = blockIdx.x * 256 + tid;
    int s = -1;
    if (t < ntok) { s = seq[t]; atomicAdd(&lh[s], 1); }
    __syncthreads();
    if (tid < 20 && lh[tid] > 0) lb[tid] = atomicAdd(&g_cursor[tid], lh[tid]);
    __syncthreads();
    if (t < ntok) {
        int p = atomicAdd(&lc[s], 1);
        g_order[g_base[s] + lb[s] + p] = t;
    }
}

// ---------------- layer 1 (dense+coord merged), grouped by aa type -----------
__global__ void __launch_bounds__(512, 2)
k_l1(const float* __restrict__ W1, const int* __restrict__ cidx) {
    extern __shared__ __align__(16) float sm[];
    float* Wc  = sm;            // 42*256 = 10752
    float* C1s = sm + 10752;    // 2560
    float* E1s = sm + 13312;    // 256
    float* xs  = sm + 13568;    // 84*36 = 3024
    int*   cs  = (int*)(sm + 16592);  // 32 ints
    int tid = threadIdx.x, s = blockIdx.x;
    if (s == 0 && blockIdx.y == 0 && tid < 20) g_cursor[tid] = 0;
    for (int i = tid; i < 2560; i += 512) C1s[i] = g_C1[i];
    if (tid < 256) E1s[tid] = g_E1[s * 256 + tid];

    int cnt = g_hist[s], base = g_base[s];
    int st = cnt * blockIdx.y / 14, en = cnt * (blockIdx.y + 1) / 14;
    int lane = tid & 31, w_ = tid >> 5;
    int jq = w_ & 3, th = w_ >> 2;
    int j0 = jq * 64 + lane, j1 = j0 + 32, T0 = th * 8;
    __syncthreads();
    ull e0 = f2pack(E1s[j0], E1s[j0]);
    ull e1 = f2pack(E1s[j1], E1s[j1]);

    for (int g0 = st; g0 < en; g0 += 32) {
        int n = min(32, en - g0);
        __syncthreads();
        if (tid < 32) cs[tid] = (tid < n) ? cidx[g_order[base + g0 + tid]] : 0;
        for (int it = w_; it < 24; it += 16) {
            int kc = it % 3, tc = it / 3;
            int k = kc * 32 + lane;
            if (k < 84) {
                int tb = tc * 4;
                float v[4];
#pragma unroll
                for (int i = 0; i < 4; i++) {
                    int t = tb + i;
                    v[i] = (t < n) ? g_feat[(size_t)g_order[base + g0 + t] * 88 + k] : 0.f;
                }
                *(float4*)&xs[k * 36 + tb] = make_float4(v[0], v[1], v[2], v[3]);
            }
        }
        for (int i = tid * 4; i < 10752; i += 2048) {
            int r = i >> 8, c = i & 255;
            int src = (r < 45) ? (128 + s * 45 + r) : (1028 + r - 45);
            *(float4*)&Wc[i] = *(const float4*)&W1[src * 256 + c];
        }
        __syncthreads();
        ull a0[4], a1[4];
#pragma unroll
        for (int u = 0; u < 4; u++) {
            int ca = cs[T0 + 2 * u], cb = cs[T0 + 2 * u + 1];
            a0[u] = fadd2(e0, f2pack(C1s[ca * 256 + j0], C1s[cb * 256 + j0]));
            a1[u] = fadd2(e1, f2pack(C1s[ca * 256 + j1], C1s[cb * 256 + j1]));
        }
#pragma unroll
        for (int c = 0; c < 2; c++) {
            if (c == 1) {
                __syncthreads();
                for (int i = tid * 4; i < 10752; i += 2048) {
                    int r = 42 + (i >> 8), cc2 = i & 255;
                    int src = (r < 45) ? (128 + s * 45 + r) : (1028 + r - 45);
                    *(float4*)&Wc[i] = *(const float4*)&W1[src * 256 + cc2];
                }
                __syncthreads();
            }
#pragma unroll 4
            for (int kk = 0; kk < 42; kk++) {
                int k = c * 42 + kk;
                float w0 = Wc[kk * 256 + j0], w1 = Wc[kk * 256 + j1];
                ull wd0 = f2pack(w0, w0), wd1 = f2pack(w1, w1);
                const ulonglong2* xr = (const ulonglong2*)&xs[k * 36 + T0];
                ulonglong2 xa = xr[0], xb = xr[1];
                a0[0] = ffma2(xa.x, wd0, a0[0]); a1[0] = ffma2(xa.x, wd1, a1[0]);
                a0[1] = ffma2(xa.y, wd0, a0[1]); a1[1] = ffma2(xa.y, wd1, a1[1]);
                a0[2] = ffma2(xb.x, wd0, a0[2]); a1[2] = ffma2(xb.x, wd1, a1[2]);
                a0[3] = ffma2(xb.y, wd0, a0[3]); a1[3] = ffma2(xb.y, wd1, a1[3]);
            }
        }
#pragma unroll
        for (int u = 0; u < 4; u++) {
            int ta = T0 + 2 * u;
            if (ta < n) {
                int pa = (base + g0 + ta) * 256;
                float va0, vb0, va1, vb1;
                f2unpack(a0[u], va0, vb0);
                f2unpack(a1[u], va1, vb1);
                g_h1[pa + j0] = fmaxf(va0, 0.f);
                g_h1[pa + j1] = fmaxf(va1, 0.f);
                if (ta + 1 < n) {
                    g_h1[pa + 256 + j0] = fmaxf(vb0, 0.f);
                    g_h1[pa + 256 + j1] = fmaxf(vb1, 0.f);
                }
            }
        }
    }
}

// ============================================================================
// Fused MLP (layers 2,3,4) via mma.sync m16n8k16 bf16 split-precision.
// A/B tiles: [row][k], 128 rows x 128 bf16, row stride 136 bf16 (272 B).
// (R10 bug: stride was 72 < 128 -> rows overlapped. Fixed.)
// ============================================================================

#define SMSTRIDE 136

static __device__ __forceinline__ void mma16816(float* c, const uint32_t* a,
                                                const uint32_t* b) {
    asm volatile(
        "mma.sync.aligned.m16n8k16.row.col.f32.bf16.bf16.f32 "
        "{%0,%1,%2,%3}, {%4,%5,%6,%7}, {%8,%9}, {%0,%1,%2,%3};"
        : "+f"(c[0]), "+f"(c[1]), "+f"(c[2]), "+f"(c[3])
        : "r"(a[0]), "r"(a[1]), "r"(a[2]), "r"(a[3]), "r"(b[0]), "r"(b[1]));
}

static __device__ __forceinline__ void split_pair(__nv_bfloat16* hiA,
                                                  __nv_bfloat16* loA,
                                                  int r, int col,
                                                  float v0, float v1) {
    __nv_bfloat16 h0 = __float2bfloat16(v0), h1 = __float2bfloat16(v1);
    __nv_bfloat16 l0 = __float2bfloat16(v0 - __bfloat162float(h0));
    __nv_bfloat16 l1 = __float2bfloat16(v1 - __bfloat162float(h1));
    __nv_bfloat162 hp, lp;
    hp.x = h0; hp.y = h1; lp.x = l0; lp.y = l1;
    *(__nv_bfloat162*)&hiA[r * SMSTRIDE + col] = hp;
    *(__nv_bfloat162*)&loA[r * SMSTRIDE + col] = lp;
}

// PTX ISA m16n8k16 fragment tables (g = lane>>2, tg = lane&3):
//   A: a0=(g, k0+2tg) a1=(g+8, k0+2tg) a2=(g, k0+8+2tg) a3=(g+8, k0+8+2tg)
//   B: b0=(k0+2tg, n=g) b1=(k0+8+2tg, n=g)
//   C: c0=(g,2tg) c1=(g,2tg+1) c2=(g+8,2tg) c3=(g+8,2tg+1)
template <int KSTEPS>
static __device__ __forceinline__ void mma_loop(
    const __nv_bfloat16* __restrict__ Ahi, const __nv_bfloat16* __restrict__ Alo,
    const __nv_bfloat16* __restrict__ Bhi, const __nv_bfloat16* __restrict__ Blo,
    int m0, int n0, int lane, float c[2][4][4]) {
    int g = lane >> 2, tg = lane & 3;
#pragma unroll
    for (int ks = 0; ks < KSTEPS; ks++) {
        int k0 = ks * 16;
        int cl = k0 + tg * 2, ch2 = cl + 8;
        uint32_t ah[2][4], al[2][4], bh[4][2], bl[4][2];
#pragma unroll
        for (int mt = 0; mt < 2; mt++) {
            int r0 = (m0 + mt * 16 + g) * SMSTRIDE;
            int r1 = r0 + 8 * SMSTRIDE;
            ah[mt][0] = *(const uint32_t*)&Ahi[r0 + cl];
            ah[mt][1] = *(const uint32_t*)&Ahi[r1 + cl];
            ah[mt][2] = *(const uint32_t*)&Ahi[r0 + ch2];
            ah[mt][3] = *(const uint32_t*)&Ahi[r1 + ch2];
            al[mt][0] = *(const uint32_t*)&Alo[r0 + cl];
            al[mt][1] = *(const uint32_t*)&Alo[r1 + cl];
            al[mt][2] = *(const uint32_t*)&Alo[r0 + ch2];
            al[mt][3] = *(const uint32_t*)&Alo[r1 + ch2];
        }
#pragma unroll
        for (int nt = 0; nt < 4; nt++) {
            int rn = (n0 + nt * 8 + g) * SMSTRIDE;
            bh[nt][0] = *(const uint32_t*)&Bhi[rn + cl];
            bh[nt][1] = *(const uint32_t*)&Bhi[rn + ch2];
            bl[nt][0] = *(const uint32_t*)&Blo[rn + cl];
            bl[nt][1] = *(const uint32_t*)&Blo[rn + ch2];
        }
#pragma unroll
        for (int mt = 0; mt < 2; mt++)
#pragma unroll
            for (int nt = 0; nt < 4; nt++) {
                mma16816(c[mt][nt], ah[mt], bh[nt]);
                mma16816(c[mt][nt], ah[mt], bl[nt]);
                mma16816(c[mt][nt], al[mt], bh[nt]);
            }
    }
}

// smem tile byte sizes/offsets (stride 136 bf16 = 272 B per row, 128 rows)
#define TILE_B 34816
#define OFF_ALO (TILE_B)
#define OFF_BHI (TILE_B * 2)
#define OFF_BLO (TILE_B * 3)
#define OFF_B2S (TILE_B * 4)            // 139264
#define OFF_B3S (OFF_B2S + 512)
#define OFF_B4S (OFF_B3S + 512)
#define OFF_OSX (OFF_B4S + 512)
#define SMEM_MLP_BYTES (OFF_OSX + 512)  // 141312

__global__ void __launch_bounds__(512)
k_mlp(const float* __restrict__ W2, const float* __restrict__ b2,
      const float* __restrict__ W3, const float* __restrict__ b3,
      const float* __restrict__ W4, const float* __restrict__ b4,
      float* __restrict__ out, int ntok) {
    extern __shared__ __align__(16) char smem[];
    __nv_bfloat16* Ahi = (__nv_bfloat16*)(smem);
    __nv_bfloat16* Alo = (__nv_bfloat16*)(smem + OFF_ALO);
    __nv_bfloat16* Bhi = (__nv_bfloat16*)(smem + OFF_BHI);
    __nv_bfloat16* Blo = (__nv_bfloat16*)(smem + OFF_BLO);
    float* b2s = (float*)(smem + OFF_B2S);
    float* b3s = (float*)(smem + OFF_B3S);
    float* b4s = (float*)(smem + OFF_B4S);
    int*   os  = (int*)(smem + OFF_OSX);

    int tid = threadIdx.x, wid = tid >> 5, lane = tid & 31;
    int m0 = (wid >> 2) * 32, n0 = (wid & 3) * 32;
    int t0 = blockIdx.x * 128;
    if (blockIdx.x == 0 && tid < 20) g_hist[tid] = 0;   // reset for next replay
    if (tid < 128) {
        b2s[tid] = b2[tid]; b3s[tid] = b3[tid]; b4s[tid] = b4[tid];
        os[tid] = (t0 + tid < ntok) ? g_order[t0 + tid] : 0;
    }

    float c[2][4][4];
#pragma unroll
    for (int mt = 0; mt < 2; mt++)
#pragma unroll
        for (int nt = 0; nt < 4; nt++)
#pragma unroll
            for (int i = 0; i < 4; i++) c[mt][nt][i] = 0.f;

    // ---------------- L2: K=256 in two chunks of 128 -------------------------
    for (int ch = 0; ch < 2; ch++) {
        if (ch) __syncthreads();   // prev chunk readers done
        for (int p = tid; p < 8192; p += 512) {   // A: h1 rows (coalesced)
            int row = p >> 6, cp = (p & 63) * 2;
            float2 v = make_float2(0.f, 0.f);
            if (t0 + row < ntok)
                v = *(const float2*)&g_h1[(size_t)(t0 + row) * 256 + ch * 128 + cp];
            split_pair(Ahi, Alo, row, cp, v.x, v.y);
        }
        for (int p = tid; p < 8192; p += 512) {   // B[j][k] = W2[k][j]
            int j = p & 127, kp = (p >> 7) * 2;
            int k = ch * 128 + kp;
            split_pair(Bhi, Blo, j, kp,
                       W2[(size_t)k * 128 + j], W2[(size_t)(k + 1) * 128 + j]);
        }
        __syncthreads();
        mma_loop<8>(Ahi, Alo, Bhi, Blo, m0, n0, lane, c);
    }

    // ---------------- L3 and L4 ---------------------------------------------
#pragma unroll 1
    for (int layer = 0; layer < 2; layer++) {
        const float* Wn = (layer == 0) ? W3 : W4;
        const float* bs = (layer == 0) ? b2s : b3s;
        __syncthreads();   // all warps' mainloop done (A/B free)
        // epilogue: bias + relu, split-store into A tile
#pragma unroll
        for (int mt = 0; mt < 2; mt++)
#pragma unroll
            for (int nt = 0; nt < 4; nt++) {
                int col = n0 + nt * 8 + (lane & 3) * 2;
                int r = m0 + mt * 16 + (lane >> 2);
                float bv0 = bs[col], bv1 = bs[col + 1];
                split_pair(Ahi, Alo, r, col,
                           fmaxf(c[mt][nt][0] + bv0, 0.f),
                           fmaxf(c[mt][nt][1] + bv1, 0.f));
                split_pair(Ahi, Alo, r + 8, col,
                           fmaxf(c[mt][nt][2] + bv0, 0.f),
                           fmaxf(c[mt][nt][3] + bv1, 0.f));
#pragma unroll
                for (int i = 0; i < 4; i++) c[mt][nt][i] = 0.f;
            }
        for (int p = tid; p < 8192; p += 512) {   // B[j][k] = Wn[k][j]
            int j = p & 127, kp = (p >> 7) * 2;
            split_pair(Bhi, Blo, j, kp,
                       Wn[(size_t)kp * 128 + j], Wn[(size_t)(kp + 1) * 128 + j]);
        }
        __syncthreads();
        mma_loop<8>(Ahi, Alo, Bhi, Blo, m0, n0, lane, c);
    }

    // ---------------- final epilogue: + b4 -> out (un-sorted) ----------------
#pragma unroll
    for (int mt = 0; mt < 2; mt++)
#pragma unroll
        for (int nt = 0; nt < 4; nt++) {
            int col = n0 + nt * 8 + (lane & 3) * 2;
            int r = m0 + mt * 16 + (lane >> 2);
            float bv0 = b4s[col], bv1 = b4s[col + 1];
            if (t0 + r < ntok) {
                float2 v = make_float2(c[mt][nt][0] + bv0, c[mt][nt][1] + bv1);
                *(float2*)&out[(size_t)os[r] * 128 + col] = v;
            }
            if (t0 + r + 8 < ntok) {
                float2 v = make_float2(c[mt][nt][2] + bv0, c[mt][nt][3] + bv1);
                *(float2*)&out[(size_t)os[r + 8] * 128 + col] = v;
            }
        }
}

// ---------------- launch ----------------------------------------------------
extern "C" void kernel_launch(void* const* d_in, const int* in_sizes, int n_in,
                              void* d_out, int out_size) {
    const int*   seq    = (const int*)  d_in[0];
    const float* xyz    = (const float*)d_in[1];
    const float* dih    = (const float*)d_in[2];
    const int*   cidx   = (const int*)  d_in[3];
    const float* ori    = (const float*)d_in[4];
    /* d_in[5] = atom_mask : unused by reference */
    const float* aa_emb = (const float*)d_in[6];
    const float* ch_emb = (const float*)d_in[7];
    const float* W1 = (const float*)d_in[8];
    const float* b1 = (const float*)d_in[9];
    const float* W2 = (const float*)d_in[10];
    const float* b2 = (const float*)d_in[11];
    const float* W3 = (const float*)d_in[12];
    const float* b3 = (const float*)d_in[13];
    const float* W4 = (const float*)d_in[14];
    const float* b4 = (const float*)d_in[15];
    float* out = (float*)d_out;
    int ntok = in_sizes[0];
    if (ntok > MAXTOK) ntok = MAXTOK;

    int nfeatblk = (ntok + 255) / 256;
    int nblk128 = (ntok + 127) / 128;
    const int SMEM1 = (16592 + 32) * 4;   // 66496 B
    cudaFuncSetAttribute(k_l1,  cudaFuncAttributeMaxDynamicSharedMemorySize, SMEM1);
    cudaFuncSetAttribute(k_mlp, cudaFuncAttributeMaxDynamicSharedMemorySize,
                         SMEM_MLP_BYTES);

    k_setup<<<30 + nfeatblk, 256>>>(aa_emb, ch_emb, W1, b1, xyz, ori, dih, seq,
                                    ntok, nfeatblk);
    k_scatter<<<(ntok + 255) / 256, 256>>>(seq, ntok);
    k_l1<<<dim3(20, 14), 512, SMEM1>>>(W1, cidx);
    k_mlp<<<nblk128, 512, SMEM_MLP_BYTES>>>(W2, b2, W3, b3, W4, b4, out, ntok);
}

// round 12
// speedup vs baseline: 1.5404x; 1.0155x over previous
#include <cuda_runtime.h>
#include <cuda_bf16.h>
#include <cstdint>

#define MAXTOK 16384

// ---------------- scratch (device globals; no allocation allowed) ----------
__device__ float g_feat[MAXTOK * 88];   // [tok][88]: 0..44 coord, 45..83 dihedral
__device__ float g_h1[MAXTOK * 256];    // sorted-token order (fp32)
__device__ float g_E1[20 * 256];
__device__ float g_C1[10 * 256];
__device__ int g_hist[20];
__device__ int g_base[20];
__device__ int g_cursor[20];
__device__ int g_order[MAXTOK];         // sorted pos -> original token
__device__ int g_done;

typedef unsigned long long ull;

static __device__ __forceinline__ ull f2pack(float lo, float hi) {
    ull r; asm("mov.b64 %0,{%1,%2};" : "=l"(r) : "f"(lo), "f"(hi)); return r;
}
static __device__ __forceinline__ void f2unpack(ull v, float& lo, float& hi) {
    asm("mov.b64 {%0,%1},%2;" : "=f"(lo), "=f"(hi) : "l"(v));
}
static __device__ __forceinline__ ull ffma2(ull a, ull b, ull c) {
    ull d; asm("fma.rn.f32x2 %0,%1,%2,%3;" : "=l"(d) : "l"(a), "l"(b), "l"(c)); return d;
}
static __device__ __forceinline__ ull fadd2(ull a, ull b) {
    ull d; asm("add.rn.f32x2 %0,%1,%2;" : "=l"(d) : "l"(a), "l"(b)); return d;
}
static __device__ __forceinline__ uint32_t smem_u32(const void* p) {
    uint32_t a;
    asm("{ .reg .u64 t; cvta.to.shared.u64 t, %1; cvt.u32.u64 %0, t; }" : "=r"(a) : "l"(p));
    return a;
}

// ---------------- setup: E1/C1 tables + per-token features + hist + scan ----
__global__ void __launch_bounds__(256)
k_setup(const float* __restrict__ aa_emb, const float* __restrict__ ch_emb,
        const float* __restrict__ W1, const float* __restrict__ b1,
        const float* __restrict__ xyz, const float* __restrict__ ori,
        const float* __restrict__ dih, const int* __restrict__ seq,
        int ntok, int nfeatblk) {
    int b = blockIdx.x, tid = threadIdx.x;
    if (b < 30) {
        int j = tid;
        if (b < 20) {
            float acc = b1[j];
#pragma unroll 8
            for (int k = 0; k < 128; k++) acc += aa_emb[b * 128 + k] * W1[k * 256 + j];
            g_E1[b * 256 + j] = acc;
        } else {
            int c = b - 20;
            float acc = 0.f;
            if (c != 0) {
#pragma unroll 8
                for (int k = 0; k < 128; k++)
                    acc += ch_emb[c * 128 + k] * W1[(1067 + k) * 256 + j];
            }
            g_C1[c * 256 + j] = acc;
        }
        return;
    }
    int t = (b - 30) * 256 + tid;
    if (t < ntok) {
        const float* X = xyz + t * 45;
        float ca0 = X[3], ca1 = X[4], ca2 = X[5];   // CA_IDX = 1
        float o[9];
#pragma unroll
        for (int i = 0; i < 9; i++) o[i] = ori[t * 9 + i];
        float* F = g_feat + t * 88;
#pragma unroll
        for (int a = 0; a < 15; a++) {
            float rx = X[a * 3 + 0] - ca0;
            float ry = X[a * 3 + 1] - ca1;
            float rz = X[a * 3 + 2] - ca2;
#pragma unroll
            for (int i = 0; i < 3; i++)
                F[a * 3 + i] = o[i] * rx + o[3 + i] * ry + o[6 + i] * rz;
        }
        const float fb[6] = {1.f, 2.f, 3.f, 1.f, 0.5f, 1.f / 3.f};
#pragma unroll
        for (int d = 0; d < 3; d++) {
            float x = dih[t * 3 + d];
            int bo = 45 + d * 13;
            F[bo] = x;
#pragma unroll
            for (int u = 0; u < 6; u++) {
                F[bo + 1 + u] = sinf(fb[u] * x);
                F[bo + 7 + u] = cosf(fb[u] * x);
            }
        }
        atomicAdd(&g_hist[seq[t]], 1);
    }
    __syncthreads();
    if (tid == 0) {
        __threadfence();
        if (atomicAdd(&g_done, 1) == nfeatblk - 1) {
            __threadfence();
            int s = 0;
            for (int i = 0; i < 20; i++) {
                int h = atomicAdd(&g_hist[i], 0);
                g_base[i] = s; s += h;
            }
            atomicExch(&g_done, 0);
        }
    }
}

// ---------------- block-aggregated counting-sort scatter ---------------------
__global__ void __launch_bounds__(256)
k_scatter(const int* __restrict__ seq, int ntok) {
    __shared__ int lh[20], lb[20], lc[20];
    int tid = threadIdx.x;
    if (tid < 20) { lh[tid] = 0; lc[tid] = 0; }
    __syncthreads();
    int t = blockIdx.x * 256 + tid;
    int s = -1;
    if (t < ntok) { s = seq[t]; atomicAdd(&lh[s], 1); }
    __syncthreads();
    if (tid < 20 && lh[tid] > 0) lb[tid] = atomicAdd(&g_cursor[tid], lh[tid]);
    __syncthreads();
    if (t < ntok) {
        int p = atomicAdd(&lc[s], 1);
        g_order[g_base[s] + lb[s] + p] = t;
    }
}

// ---------------- layer 1 (dense+coord merged), grouped by aa type -----------
__global__ void __launch_bounds__(512, 2)
k_l1(const float* __restrict__ W1, const int* __restrict__ cidx) {
    extern __shared__ __align__(16) float sm[];
    float* Wc  = sm;            // 42*256 = 10752
    float* C1s = sm + 10752;    // 2560
    float* E1s = sm + 13312;    // 256
    float* xs  = sm + 13568;    // 84*36 = 3024
    int*   cs  = (int*)(sm + 16592);  // 32 ints
    int tid = threadIdx.x, s = blockIdx.x;
    if (s == 0 && blockIdx.y == 0 && tid < 20) g_cursor[tid] = 0;
    for (int i = tid; i < 2560; i += 512) C1s[i] = g_C1[i];
    if (tid < 256) E1s[tid] = g_E1[s * 256 + tid];

    int cnt = g_hist[s], base = g_base[s];
    int st = cnt * blockIdx.y / 14, en = cnt * (blockIdx.y + 1) / 14;
    int lane = tid & 31, w_ = tid >> 5;
    int jq = w_ & 3, th = w_ >> 2;
    int j0 = jq * 64 + lane, j1 = j0 + 32, T0 = th * 8;
    __syncthreads();
    ull e0 = f2pack(E1s[j0], E1s[j0]);
    ull e1 = f2pack(E1s[j1], E1s[j1]);

    for (int g0 = st; g0 < en; g0 += 32) {
        int n = min(32, en - g0);
        __syncthreads();
        if (tid < 32) cs[tid] = (tid < n) ? cidx[g_order[base + g0 + tid]] : 0;
        for (int it = w_; it < 24; it += 16) {
            int kc = it % 3, tc = it / 3;
            int k = kc * 32 + lane;
            if (k < 84) {
                int tb = tc * 4;
                float v[4];
#pragma unroll
                for (int i = 0; i < 4; i++) {
                    int t = tb + i;
                    v[i] = (t < n) ? g_feat[(size_t)g_order[base + g0 + t] * 88 + k] : 0.f;
                }
                *(float4*)&xs[k * 36 + tb] = make_float4(v[0], v[1], v[2], v[3]);
            }
        }
        for (int i = tid * 4; i < 10752; i += 2048) {
            int r = i >> 8, c = i & 255;
            int src = (r < 45) ? (128 + s * 45 + r) : (1028 + r - 45);
            *(float4*)&Wc[i] = *(const float4*)&W1[src * 256 + c];
        }
        __syncthreads();
        ull a0[4], a1[4];
#pragma unroll
        for (int u = 0; u < 4; u++) {
            int ca = cs[T0 + 2 * u], cb = cs[T0 + 2 * u + 1];
            a0[u] = fadd2(e0, f2pack(C1s[ca * 256 + j0], C1s[cb * 256 + j0]));
            a1[u] = fadd2(e1, f2pack(C1s[ca * 256 + j1], C1s[cb * 256 + j1]));
        }
#pragma unroll
        for (int c = 0; c < 2; c++) {
            if (c == 1) {
                __syncthreads();
                for (int i = tid * 4; i < 10752; i += 2048) {
                    int r = 42 + (i >> 8), cc2 = i & 255;
                    int src = (r < 45) ? (128 + s * 45 + r) : (1028 + r - 45);
                    *(float4*)&Wc[i] = *(const float4*)&W1[src * 256 + cc2];
                }
                __syncthreads();
            }
#pragma unroll 4
            for (int kk = 0; kk < 42; kk++) {
                int k = c * 42 + kk;
                float w0 = Wc[kk * 256 + j0], w1 = Wc[kk * 256 + j1];
                ull wd0 = f2pack(w0, w0), wd1 = f2pack(w1, w1);
                const ulonglong2* xr = (const ulonglong2*)&xs[k * 36 + T0];
                ulonglong2 xa = xr[0], xb = xr[1];
                a0[0] = ffma2(xa.x, wd0, a0[0]); a1[0] = ffma2(xa.x, wd1, a1[0]);
                a0[1] = ffma2(xa.y, wd0, a0[1]); a1[1] = ffma2(xa.y, wd1, a1[1]);
                a0[2] = ffma2(xb.x, wd0, a0[2]); a1[2] = ffma2(xb.x, wd1, a1[2]);
                a0[3] = ffma2(xb.y, wd0, a0[3]); a1[3] = ffma2(xb.y, wd1, a1[3]);
            }
        }
#pragma unroll
        for (int u = 0; u < 4; u++) {
            int ta = T0 + 2 * u;
            if (ta < n) {
                int pa = (base + g0 + ta) * 256;
                float va0, vb0, va1, vb1;
                f2unpack(a0[u], va0, vb0);
                f2unpack(a1[u], va1, vb1);
                g_h1[pa + j0] = fmaxf(va0, 0.f);
                g_h1[pa + j1] = fmaxf(va1, 0.f);
                if (ta + 1 < n) {
                    g_h1[pa + 256 + j0] = fmaxf(vb0, 0.f);
                    g_h1[pa + 256 + j1] = fmaxf(vb1, 0.f);
                }
            }
        }
    }
}

// ============================================================================
// Fused MLP (layers 2,3,4) via mma.sync m16n8k16 bf16 split-precision.
// A/B tiles: [row][k], 128 rows x 128 bf16, row stride 136 bf16 (272 B).
// Fragments via ldmatrix.x4 (layout validated in R11; R9's mapping was
// correct — the old stride-72 overlap was the bug).
// ============================================================================

#define SMSTRIDE 136

#define LDSM_X4(r0, r1, r2, r3, addr) \
    asm volatile("ldmatrix.sync.aligned.m8n8.x4.shared.b16 {%0,%1,%2,%3}, [%4];" \
        : "=r"(r0), "=r"(r1), "=r"(r2), "=r"(r3) : "r"(addr))

static __device__ __forceinline__ void mma16816(float* c, const uint32_t* a,
                                                const uint32_t* b) {
    asm volatile(
        "mma.sync.aligned.m16n8k16.row.col.f32.bf16.bf16.f32 "
        "{%0,%1,%2,%3}, {%4,%5,%6,%7}, {%8,%9}, {%0,%1,%2,%3};"
        : "+f"(c[0]), "+f"(c[1]), "+f"(c[2]), "+f"(c[3])
        : "r"(a[0]), "r"(a[1]), "r"(a[2]), "r"(a[3]), "r"(b[0]), "r"(b[1]));
}

static __device__ __forceinline__ void split_pair(__nv_bfloat16* hiA,
                                                  __nv_bfloat16* loA,
                                                  int r, int col,
                                                  float v0, float v1) {
    __nv_bfloat16 h0 = __float2bfloat16(v0), h1 = __float2bfloat16(v1);
    __nv_bfloat16 l0 = __float2bfloat16(v0 - __bfloat162float(h0));
    __nv_bfloat16 l1 = __float2bfloat16(v1 - __bfloat162float(h1));
    __nv_bfloat162 hp, lp;
    hp.x = h0; hp.y = h1; lp.x = l0; lp.y = l1;
    *(__nv_bfloat162*)&hiA[r * SMSTRIDE + col] = hp;
    *(__nv_bfloat162*)&loA[r * SMSTRIDE + col] = lp;
}

template <int KSTEPS>
static __device__ __forceinline__ void mma_loop(uint32_t aHi, uint32_t aLo,
                                                uint32_t bHi, uint32_t bLo,
                                                int m0, int n0, int lane,
                                                float c[2][4][4]) {
    int arow = lane & 15, akhalf = (lane >> 4) << 3;
    int bn = ((lane >> 4) << 3) + (lane & 7), bkhalf = ((lane >> 3) & 1) << 3;
#pragma unroll
    for (int ks = 0; ks < KSTEPS; ks++) {
        int k0 = ks * 16;
        uint32_t ah[2][4], al[2][4], bh[4][2], bl[4][2];
#pragma unroll
        for (int mt = 0; mt < 2; mt++) {
            uint32_t off =
                (uint32_t)(((m0 + mt * 16 + arow) * SMSTRIDE + k0 + akhalf) * 2);
            LDSM_X4(ah[mt][0], ah[mt][1], ah[mt][2], ah[mt][3], aHi + off);
            LDSM_X4(al[mt][0], al[mt][1], al[mt][2], al[mt][3], aLo + off);
        }
#pragma unroll
        for (int ng = 0; ng < 2; ng++) {
            uint32_t off =
                (uint32_t)(((n0 + ng * 16 + bn) * SMSTRIDE + k0 + bkhalf) * 2);
            uint32_t r0, r1, r2, r3;
            LDSM_X4(r0, r1, r2, r3, bHi + off);
            bh[ng * 2][0] = r0;     bh[ng * 2][1] = r1;
            bh[ng * 2 + 1][0] = r2; bh[ng * 2 + 1][1] = r3;
            LDSM_X4(r0, r1, r2, r3, bLo + off);
            bl[ng * 2][0] = r0;     bl[ng * 2][1] = r1;
            bl[ng * 2 + 1][0] = r2; bl[ng * 2 + 1][1] = r3;
        }
#pragma unroll
        for (int mt = 0; mt < 2; mt++)
#pragma unroll
            for (int nt = 0; nt < 4; nt++) {
                mma16816(c[mt][nt], ah[mt], bh[nt]);
                mma16816(c[mt][nt], ah[mt], bl[nt]);
                mma16816(c[mt][nt], al[mt], bh[nt]);
            }
    }
}

// smem tile byte sizes/offsets (stride 136 bf16 = 272 B per row, 128 rows)
#define TILE_B 34816
#define OFF_ALO (TILE_B)
#define OFF_BHI (TILE_B * 2)
#define OFF_BLO (TILE_B * 3)
#define OFF_B2S (TILE_B * 4)            // 139264
#define OFF_B3S (OFF_B2S + 512)
#define OFF_B4S (OFF_B3S + 512)
#define OFF_OSX (OFF_B4S + 512)
#define SMEM_MLP_BYTES (OFF_OSX + 512)  // 141312

__global__ void __launch_bounds__(512)
k_mlp(const float* __restrict__ W2, const float* __restrict__ b2,
      const float* __restrict__ W3, const float* __restrict__ b3,
      const float* __restrict__ W4, const float* __restrict__ b4,
      float* __restrict__ out, int ntok) {
    extern __shared__ __align__(16) char smem[];
    __nv_bfloat16* Ahi = (__nv_bfloat16*)(smem);
    __nv_bfloat16* Alo = (__nv_bfloat16*)(smem + OFF_ALO);
    __nv_bfloat16* Bhi = (__nv_bfloat16*)(smem + OFF_BHI);
    __nv_bfloat16* Blo = (__nv_bfloat16*)(smem + OFF_BLO);
    float* b2s = (float*)(smem + OFF_B2S);
    float* b3s = (float*)(smem + OFF_B3S);
    float* b4s = (float*)(smem + OFF_B4S);
    int*   os  = (int*)(smem + OFF_OSX);
    uint32_t aHi = smem_u32(Ahi), aLo = smem_u32(Alo);
    uint32_t bHi = smem_u32(Bhi), bLo = smem_u32(Blo);

    int tid = threadIdx.x, wid = tid >> 5, lane = tid & 31;
    int m0 = (wid >> 2) * 32, n0 = (wid & 3) * 32;
    int t0 = blockIdx.x * 128;
    if (blockIdx.x == 0 && tid < 20) g_hist[tid] = 0;   // reset for next replay
    if (tid < 128) {
        b2s[tid] = b2[tid]; b3s[tid] = b3[tid]; b4s[tid] = b4[tid];
        os[tid] = (t0 + tid < ntok) ? g_order[t0 + tid] : 0;
    }

    float c[2][4][4];
#pragma unroll
    for (int mt = 0; mt < 2; mt++)
#pragma unroll
        for (int nt = 0; nt < 4; nt++)
#pragma unroll
            for (int i = 0; i < 4; i++) c[mt][nt][i] = 0.f;

    // ---------------- L2: K=256 in two chunks of 128 -------------------------
    for (int ch = 0; ch < 2; ch++) {
        if (ch) __syncthreads();   // prev chunk readers done
        for (int p = tid; p < 8192; p += 512) {   // A: h1 rows (coalesced)
            int row = p >> 6, cp = (p & 63) * 2;
            float2 v = make_float2(0.f, 0.f);
            if (t0 + row < ntok)
                v = *(const float2*)&g_h1[(size_t)(t0 + row) * 256 + ch * 128 + cp];
            split_pair(Ahi, Alo, row, cp, v.x, v.y);
        }
        for (int p = tid; p < 8192; p += 512) {   // B[j][k] = W2[k][j]
            int j = p & 127, kp = (p >> 7) * 2;
            int k = ch * 128 + kp;
            split_pair(Bhi, Blo, j, kp,
                       W2[(size_t)k * 128 + j], W2[(size_t)(k + 1) * 128 + j]);
        }
        __syncthreads();
        mma_loop<8>(aHi, aLo, bHi, bLo, m0, n0, lane, c);
    }

    // ---------------- L3 and L4 ---------------------------------------------
#pragma unroll 1
    for (int layer = 0; layer < 2; layer++) {
        const float* Wn = (layer == 0) ? W3 : W4;
        const float* bs = (layer == 0) ? b2s : b3s;
        __syncthreads();   // all warps' mainloop done (A/B free)
        // epilogue: bias + relu, split-store into A tile
#pragma unroll
        for (int mt = 0; mt < 2; mt++)
#pragma unroll
            for (int nt = 0; nt < 4; nt++) {
                int col = n0 + nt * 8 + (lane & 3) * 2;
                int r = m0 + mt * 16 + (lane >> 2);
                float bv0 = bs[col], bv1 = bs[col + 1];
                split_pair(Ahi, Alo, r, col,
                           fmaxf(c[mt][nt][0] + bv0, 0.f),
                           fmaxf(c[mt][nt][1] + bv1, 0.f));
                split_pair(Ahi, Alo, r + 8, col,
                           fmaxf(c[mt][nt][2] + bv0, 0.f),
                           fmaxf(c[mt][nt][3] + bv1, 0.f));
#pragma unroll
                for (int i = 0; i < 4; i++) c[mt][nt][i] = 0.f;
            }
        for (int p = tid; p < 8192; p += 512) {   // B[j][k] = Wn[k][j]
            int j = p & 127, kp = (p >> 7) * 2;
            split_pair(Bhi, Blo, j, kp,
                       Wn[(size_t)kp * 128 + j], Wn[(size_t)(kp + 1) * 128 + j]);
        }
        __syncthreads();
        mma_loop<8>(aHi, aLo, bHi, bLo, m0, n0, lane, c);
    }

    // ---------------- final epilogue: + b4 -> out (un-sorted) ----------------
#pragma unroll
    for (int mt = 0; mt < 2; mt++)
#pragma unroll
        for (int nt = 0; nt < 4; nt++) {
            int col = n0 + nt * 8 + (lane & 3) * 2;
            int r = m0 + mt * 16 + (lane >> 2);
            float bv0 = b4s[col], bv1 = b4s[col + 1];
            if (t0 + r < ntok) {
                float2 v = make_float2(c[mt][nt][0] + bv0, c[mt][nt][1] + bv1);
                *(float2*)&out[(size_t)os[r] * 128 + col] = v;
            }
            if (t0 + r + 8 < ntok) {
                float2 v = make_float2(c[mt][nt][2] + bv0, c[mt][nt][3] + bv1);
                *(float2*)&out[(size_t)os[r + 8] * 128 + col] = v;
            }
        }
}

// ---------------- launch ----------------------------------------------------
extern "C" void kernel_launch(void* const* d_in, const int* in_sizes, int n_in,
                              void* d_out, int out_size) {
    const int*   seq    = (const int*)  d_in[0];
    const float* xyz    = (const float*)d_in[1];
    const float* dih    = (const float*)d_in[2];
    const int*   cidx   = (const int*)  d_in[3];
    const float* ori    = (const float*)d_in[4];
    /* d_in[5] = atom_mask : unused by reference */
    const float* aa_emb = (const float*)d_in[6];
    const float* ch_emb = (const float*)d_in[7];
    const float* W1 = (const float*)d_in[8];
    const float* b1 = (const float*)d_in[9];
    const float* W2 = (const float*)d_in[10];
    const float* b2 = (const float*)d_in[11];
    const float* W3 = (const float*)d_in[12];
    const float* b3 = (const float*)d_in[13];
    const float* W4 = (const float*)d_in[14];
    const float* b4 = (const float*)d_in[15];
    float* out = (float*)d_out;
    int ntok = in_sizes[0];
    if (ntok > MAXTOK) ntok = MAXTOK;

    int nfeatblk = (ntok + 255) / 256;
    int nblk128 = (ntok + 127) / 128;
    const int SMEM1 = (16592 + 32) * 4;   // 66496 B
    cudaFuncSetAttribute(k_l1,  cudaFuncAttributeMaxDynamicSharedMemorySize, SMEM1);
    cudaFuncSetAttribute(k_mlp, cudaFuncAttributeMaxDynamicSharedMemorySize,
                         SMEM_MLP_BYTES);

    k_setup<<<30 + nfeatblk, 256>>>(aa_emb, ch_emb, W1, b1, xyz, ori, dih, seq,
                                    ntok, nfeatblk);
    k_scatter<<<(ntok + 255) / 256, 256>>>(seq, ntok);
    k_l1<<<dim3(20, 14), 512, SMEM1>>>(W1, cidx);
    k_mlp<<<nblk128, 512, SMEM_MLP_BYTES>>>(W2, b2, W3, b3, W4, b4, out, ntok);
}